// round 1
// baseline (speedup 1.0000x reference)
#include <cuda_runtime.h>

// Problem constants
#define NB   4
#define SEQ  1024
#define NH   16
#define DH   64
#define DM   1024
#define MROWS (NB * SEQ)

// Scratch for Q/K/V in [B, H, S, HD] layout (16 MB each; __device__ globals are
// the sanctioned scratch mechanism — no cudaMalloc allowed).
__device__ float g_q[NB * NH * SEQ * DH];
__device__ float g_k[NB * NH * SEQ * DH];
__device__ float g_v[NB * NH * SEQ * DH];

__device__ __forceinline__ float warpMax(float v) {
#pragma unroll
    for (int o = 16; o > 0; o >>= 1) v = fmaxf(v, __shfl_xor_sync(0xffffffffu, v, o));
    return v;
}
__device__ __forceinline__ float warpSum(float v) {
#pragma unroll
    for (int o = 16; o > 0; o >>= 1) v += __shfl_xor_sync(0xffffffffu, v, o);
    return v;
}

// ---------------------------------------------------------------------------
// Fused QKV projection: Y = X @ W + b, scattered to [B, H, S, HD].
// Tile 64x64x16, 256 threads, 4x4 microtile. blockIdx.z selects q/k/v.
// ---------------------------------------------------------------------------
__global__ __launch_bounds__(256) void qkv_proj_kernel(
    const float* __restrict__ X,
    const float* __restrict__ Wq, const float* __restrict__ bq,
    const float* __restrict__ Wk, const float* __restrict__ bk,
    const float* __restrict__ Wv, const float* __restrict__ bv) {
    __shared__ float As[16][68];   // A tile transposed [k][m], padded
    __shared__ float Bs[16][64];   // B tile [k][n]

    const float* W;
    const float* bias;
    float* outp;
    if (blockIdx.z == 0)      { W = Wq; bias = bq; outp = g_q; }
    else if (blockIdx.z == 1) { W = Wk; bias = bk; outp = g_k; }
    else                      { W = Wv; bias = bv; outp = g_v; }

    const int tid = threadIdx.x;
    const int tx = tid & 15, ty = tid >> 4;
    const int m0 = blockIdx.y * 64, n0 = blockIdx.x * 64;
    const int arow = tid >> 2,  acg = (tid & 3) << 2;
    const int brow = tid >> 4,  bcg = (tid & 15) << 2;

    float acc[4][4] = {};

    for (int k0 = 0; k0 < DM; k0 += 16) {
        float4 av  = *(const float4*)(X + (size_t)(m0 + arow) * DM + k0 + acg);
        float4 bv4 = *(const float4*)(W + (size_t)(k0 + brow) * DM + n0 + bcg);
        __syncthreads();
        As[acg + 0][arow] = av.x;
        As[acg + 1][arow] = av.y;
        As[acg + 2][arow] = av.z;
        As[acg + 3][arow] = av.w;
        *(float4*)(&Bs[brow][bcg]) = bv4;
        __syncthreads();
#pragma unroll
        for (int k = 0; k < 16; ++k) {
            float4 a = *(const float4*)(&As[k][ty << 2]);
            float4 b = *(const float4*)(&Bs[k][tx << 2]);
            float aa[4] = {a.x, a.y, a.z, a.w};
            float bb[4] = {b.x, b.y, b.z, b.w};
#pragma unroll
            for (int i = 0; i < 4; ++i)
#pragma unroll
                for (int j = 0; j < 4; ++j)
                    acc[i][j] = fmaf(aa[i], bb[j], acc[i][j]);
        }
    }

#pragma unroll
    for (int i = 0; i < 4; ++i) {
        const int m = m0 + (ty << 2) + i;
        const int bI = m >> 10;        // m / SEQ
        const int s  = m & (SEQ - 1);
#pragma unroll
        for (int j = 0; j < 4; ++j) {
            const int n = n0 + (tx << 2) + j;
            const int h  = n >> 6;     // n / DH
            const int hd = n & 63;
            outp[((size_t)((bI * NH + h) * SEQ + s)) * DH + hd] = acc[i][j] + bias[n];
        }
    }
}

// ---------------------------------------------------------------------------
// Attention: one CTA per (b, h, 32-q-row tile). Scores tile lives in SMEM.
//   phase 1: scores = clamp(QK^T * scale + mask, -1e4)
//   phase 2: sparsemax (even h, bisection) / softmax (odd h) per row
//   phase 3: out = weights @ V, written to [B, S, H*HD]
// ---------------------------------------------------------------------------
constexpr int TQ = 32;           // q rows per CTA
constexpr int CK = 64;           // K/V chunk rows
constexpr int NT = 256;          // threads
constexpr int PS = 68;           // padded row stride for q/kv tiles
constexpr int SMEM_FLOATS = TQ * SEQ + TQ * PS + CK * PS;
constexpr float SCALE = 0.125f;  // 64^-0.5

__global__ __launch_bounds__(NT) void attn_kernel(const float* __restrict__ mask,
                                                  float* __restrict__ out) {
    extern __shared__ float sm[];
    float* sc  = sm;                    // [TQ][SEQ]
    float* qs  = sm + TQ * SEQ;         // [TQ][PS]
    float* kvs = qs + TQ * PS;          // [CK][PS]

    const int tid = threadIdx.x;
    const int b = blockIdx.z, h = blockIdx.y;
    const int q0 = blockIdx.x * TQ;
    const int bh = b * NH + h;
    const float* Qb = g_q + ((size_t)bh * SEQ + q0) * DH;
    const float* Kb = g_k + (size_t)bh * SEQ * DH;
    const float* Vb = g_v + (size_t)bh * SEQ * DH;
    const float* mrow = mask + b * SEQ;

    // load q tile (32 x 64) into padded smem
    for (int i = tid; i < TQ * DH / 4; i += NT) {
        const int e = i << 2;
        const int qi = e >> 6, dd = e & 63;
        float4 v = *(const float4*)(Qb + e);
        qs[qi * PS + dd + 0] = v.x;
        qs[qi * PS + dd + 1] = v.y;
        qs[qi * PS + dd + 2] = v.z;
        qs[qi * PS + dd + 3] = v.w;
    }

    const int tx = tid & 15, ty = tid >> 4;
    const int qy = ty << 1, kx = tx << 2;   // 2 q-rows x 4 k-cols per thread

    // ---- phase 1: scores ----
    for (int kc = 0; kc < SEQ / CK; ++kc) {
        __syncthreads();
        for (int i = tid; i < CK * DH / 4; i += NT) {
            const int e = i << 2;
            const int r = e >> 6, dd = e & 63;
            float4 v = *(const float4*)(Kb + (size_t)kc * CK * DH + e);
            kvs[r * PS + dd + 0] = v.x;
            kvs[r * PS + dd + 1] = v.y;
            kvs[r * PS + dd + 2] = v.z;
            kvs[r * PS + dd + 3] = v.w;
        }
        __syncthreads();

        float acc[2][4] = {};
#pragma unroll
        for (int d = 0; d < DH; d += 4) {
            float4 qa = *(const float4*)(qs + qy * PS + d);
            float4 qb = *(const float4*)(qs + (qy + 1) * PS + d);
#pragma unroll
            for (int j = 0; j < 4; ++j) {
                float4 kv = *(const float4*)(kvs + (kx + j) * PS + d);
                acc[0][j] = fmaf(qa.x, kv.x, acc[0][j]);
                acc[0][j] = fmaf(qa.y, kv.y, acc[0][j]);
                acc[0][j] = fmaf(qa.z, kv.z, acc[0][j]);
                acc[0][j] = fmaf(qa.w, kv.w, acc[0][j]);
                acc[1][j] = fmaf(qb.x, kv.x, acc[1][j]);
                acc[1][j] = fmaf(qb.y, kv.y, acc[1][j]);
                acc[1][j] = fmaf(qb.z, kv.z, acc[1][j]);
                acc[1][j] = fmaf(qb.w, kv.w, acc[1][j]);
            }
        }
#pragma unroll
        for (int i = 0; i < 2; ++i)
#pragma unroll
            for (int j = 0; j < 4; ++j) {
                const int kk = kc * CK + kx + j;
                float v = fmaf(acc[i][j], SCALE, mrow[kk]);
                v = fmaxf(v, -10000.0f);
                sc[(qy + i) * SEQ + kk] = v;
            }
    }
    __syncthreads();

    // ---- phase 2: sparsemax (even h) / softmax (odd h), one warp per row ----
    const bool sparse = ((h & 1) == 0);
    const int warp = tid >> 5, lane = tid & 31;
    for (int r = warp; r < TQ; r += NT / 32) {
        float* row = sc + r * SEQ;
        float zr[32];
#pragma unroll
        for (int j = 0; j < 32; ++j) zr[j] = row[j * 32 + lane];
        float mx = -1e30f;
#pragma unroll
        for (int j = 0; j < 32; ++j) mx = fmaxf(mx, zr[j]);
        mx = warpMax(mx);

        if (sparse) {
            // Solve sum(max(z - tau, 0)) = 1 for tau in [mx - 1, mx].
            float lo = mx - 1.0f, hi = mx;
            for (int it = 0; it < 26; ++it) {
                const float tau = 0.5f * (lo + hi);
                float s = 0.f;
#pragma unroll
                for (int j = 0; j < 32; ++j) s += fmaxf(zr[j] - tau, 0.f);
                s = warpSum(s);
                if (s > 1.0f) lo = tau; else hi = tau;
            }
            // exact solve on the identified support
            const float tau = 0.5f * (lo + hi);
            float ssum = 0.f, cnt = 0.f;
#pragma unroll
            for (int j = 0; j < 32; ++j)
                if (zr[j] > tau) { ssum += zr[j]; cnt += 1.f; }
            ssum = warpSum(ssum);
            cnt  = warpSum(cnt);
            const float tf = (cnt >= 0.5f) ? (ssum - 1.0f) / cnt : tau;
#pragma unroll
            for (int j = 0; j < 32; ++j) row[j * 32 + lane] = fmaxf(zr[j] - tf, 0.f);
        } else {
            float s = 0.f;
#pragma unroll
            for (int j = 0; j < 32; ++j) { zr[j] = __expf(zr[j] - mx); s += zr[j]; }
            s = warpSum(s);
            const float inv = 1.0f / s;
#pragma unroll
            for (int j = 0; j < 32; ++j) row[j * 32 + lane] = zr[j] * inv;
        }
    }

    // ---- phase 3: out = weights @ V ----
    float oacc[2][4] = {};
    for (int kc = 0; kc < SEQ / CK; ++kc) {
        __syncthreads();
        for (int i = tid; i < CK * DH / 4; i += NT) {
            const int e = i << 2;
            const int r = e >> 6, dd = e & 63;
            float4 v = *(const float4*)(Vb + (size_t)kc * CK * DH + e);
            kvs[r * PS + dd + 0] = v.x;
            kvs[r * PS + dd + 1] = v.y;
            kvs[r * PS + dd + 2] = v.z;
            kvs[r * PS + dd + 3] = v.w;
        }
        __syncthreads();
#pragma unroll 4
        for (int k = 0; k < CK; ++k) {
            const float w0 = sc[qy * SEQ + kc * CK + k];
            const float w1 = sc[(qy + 1) * SEQ + kc * CK + k];
            float4 vv = *(const float4*)(kvs + k * PS + kx);
            oacc[0][0] = fmaf(w0, vv.x, oacc[0][0]);
            oacc[0][1] = fmaf(w0, vv.y, oacc[0][1]);
            oacc[0][2] = fmaf(w0, vv.z, oacc[0][2]);
            oacc[0][3] = fmaf(w0, vv.w, oacc[0][3]);
            oacc[1][0] = fmaf(w1, vv.x, oacc[1][0]);
            oacc[1][1] = fmaf(w1, vv.y, oacc[1][1]);
            oacc[1][2] = fmaf(w1, vv.z, oacc[1][2]);
            oacc[1][3] = fmaf(w1, vv.w, oacc[1][3]);
        }
    }

    // write [B, S, H*HD]
    float* op = out + ((size_t)(b * SEQ + q0 + qy)) * DM + h * DH + kx;
    *(float4*)op        = make_float4(oacc[0][0], oacc[0][1], oacc[0][2], oacc[0][3]);
    *(float4*)(op + DM) = make_float4(oacc[1][0], oacc[1][1], oacc[1][2], oacc[1][3]);
}

// ---------------------------------------------------------------------------
extern "C" void kernel_launch(void* const* d_in, const int* in_sizes, int n_in,
                              void* d_out, int out_size) {
    const float* X    = (const float*)d_in[0];
    const float* Wq   = (const float*)d_in[1];
    const float* bq   = (const float*)d_in[2];
    const float* Wk   = (const float*)d_in[3];
    const float* bk   = (const float*)d_in[4];
    const float* Wv   = (const float*)d_in[5];
    const float* bv   = (const float*)d_in[6];
    const float* mask = (const float*)d_in[7];
    float* out = (float*)d_out;

    dim3 gp(DM / 64, MROWS / 64, 3);
    qkv_proj_kernel<<<gp, 256>>>(X, Wq, bq, Wk, bk, Wv, bv);

    cudaFuncSetAttribute(attn_kernel, cudaFuncAttributeMaxDynamicSharedMemorySize,
                         SMEM_FLOATS * (int)sizeof(float));
    dim3 ga(SEQ / TQ, NH, NB);
    attn_kernel<<<ga, NT, SMEM_FLOATS * sizeof(float)>>>(mask, out);
}

// round 2
// speedup vs baseline: 1.6906x; 1.6906x over previous
#include <cuda_runtime.h>

// Problem constants
#define NB   4
#define SEQ  1024
#define NH   16
#define DH   64
#define DM   1024
#define MROWS (NB * SEQ)

// Scratch for Q/K/V in [B, H, S, HD] layout.
__device__ float g_q[NB * NH * SEQ * DH];
__device__ float g_k[NB * NH * SEQ * DH];
__device__ float g_v[NB * NH * SEQ * DH];

__device__ __forceinline__ float warpMax(float v) {
#pragma unroll
    for (int o = 16; o > 0; o >>= 1) v = fmaxf(v, __shfl_xor_sync(0xffffffffu, v, o));
    return v;
}
__device__ __forceinline__ float warpSum(float v) {
#pragma unroll
    for (int o = 16; o > 0; o >>= 1) v += __shfl_xor_sync(0xffffffffu, v, o);
    return v;
}

// ---------------------------------------------------------------------------
// Fused QKV projection: Y = X @ W + b, scattered to [B, H, S, HD].
// Tile 64x64x16, 256 threads, 4x4 microtile. blockIdx.z selects q/k/v.
// ---------------------------------------------------------------------------
__global__ __launch_bounds__(256) void qkv_proj_kernel(
    const float* __restrict__ X,
    const float* __restrict__ Wq, const float* __restrict__ bq,
    const float* __restrict__ Wk, const float* __restrict__ bk,
    const float* __restrict__ Wv, const float* __restrict__ bv) {
    __shared__ float As[16][68];   // A tile transposed [k][m], padded
    __shared__ float Bs[16][64];   // B tile [k][n]

    const float* W;
    const float* bias;
    float* outp;
    if (blockIdx.z == 0)      { W = Wq; bias = bq; outp = g_q; }
    else if (blockIdx.z == 1) { W = Wk; bias = bk; outp = g_k; }
    else                      { W = Wv; bias = bv; outp = g_v; }

    const int tid = threadIdx.x;
    const int tx = tid & 15, ty = tid >> 4;
    const int m0 = blockIdx.y * 64, n0 = blockIdx.x * 64;
    const int arow = tid >> 2,  acg = (tid & 3) << 2;
    const int brow = tid >> 4,  bcg = (tid & 15) << 2;

    float acc[4][4] = {};

    for (int k0 = 0; k0 < DM; k0 += 16) {
        float4 av  = *(const float4*)(X + (size_t)(m0 + arow) * DM + k0 + acg);
        float4 bv4 = *(const float4*)(W + (size_t)(k0 + brow) * DM + n0 + bcg);
        __syncthreads();
        As[acg + 0][arow] = av.x;
        As[acg + 1][arow] = av.y;
        As[acg + 2][arow] = av.z;
        As[acg + 3][arow] = av.w;
        *(float4*)(&Bs[brow][bcg]) = bv4;
        __syncthreads();
#pragma unroll
        for (int k = 0; k < 16; ++k) {
            float4 a = *(const float4*)(&As[k][ty << 2]);
            float4 b = *(const float4*)(&Bs[k][tx << 2]);
            float aa[4] = {a.x, a.y, a.z, a.w};
            float bb[4] = {b.x, b.y, b.z, b.w};
#pragma unroll
            for (int i = 0; i < 4; ++i)
#pragma unroll
                for (int j = 0; j < 4; ++j)
                    acc[i][j] = fmaf(aa[i], bb[j], acc[i][j]);
        }
    }

#pragma unroll
    for (int i = 0; i < 4; ++i) {
        const int m = m0 + (ty << 2) + i;
        const int bI = m >> 10;
        const int s  = m & (SEQ - 1);
#pragma unroll
        for (int j = 0; j < 4; ++j) {
            const int n = n0 + (tx << 2) + j;
            const int h  = n >> 6;
            const int hd = n & 63;
            outp[((size_t)((bI * NH + h) * SEQ + s)) * DH + hd] = acc[i][j] + bias[n];
        }
    }
}

// ---------------------------------------------------------------------------
// Attention: one CTA per (b, h, 32-q-row tile). Scores tile lives in SMEM.
//   phase 1: scores = clamp(QK^T * scale + mask, -1e4)   [4q x 8k microtile]
//   phase 2: sparsemax (even h, bisection) / softmax (odd h) per row
//   phase 3: out = weights @ V                            [2q x 4hd, k-unroll 4]
// ---------------------------------------------------------------------------
constexpr int TQ = 32;           // q rows per CTA
constexpr int CK = 256;          // K/V chunk rows
constexpr int NT = 256;          // threads
constexpr int PS = 68;           // padded row stride (68 % 32 == 4 -> conflict-free)
constexpr int SMEM_FLOATS = TQ * SEQ + TQ * PS + CK * PS;
constexpr float SCALE = 0.125f;  // 64^-0.5

__global__ __launch_bounds__(NT) void attn_kernel(const float* __restrict__ mask,
                                                  float* __restrict__ out) {
    extern __shared__ float sm[];
    float* sc  = sm;                    // [TQ][SEQ]
    float* qs  = sm + TQ * SEQ;         // [TQ][PS]
    float* kvs = qs + TQ * PS;          // [CK][PS]

    const int tid = threadIdx.x;
    const int b = blockIdx.z, h = blockIdx.y;
    const int q0 = blockIdx.x * TQ;
    const int bh = b * NH + h;
    const float* Qb = g_q + ((size_t)bh * SEQ + q0) * DH;
    const float* Kb = g_k + (size_t)bh * SEQ * DH;
    const float* Vb = g_v + (size_t)bh * SEQ * DH;
    const float* mrow = mask + b * SEQ;

    // load q tile (32 x 64) into padded smem
#pragma unroll
    for (int i = tid; i < TQ * DH / 4; i += NT) {
        const int e = i << 2;
        const int qi = e >> 6, dd = e & 63;
        float4 v = *(const float4*)(Qb + e);
        *(float4*)(qs + qi * PS + dd) = v;
    }

    // ---- phase 1: scores.  warp tq owns q rows 4tq..4tq+3; lane tk owns
    // k columns {tk + 32j, j=0..7} of each 256-wide chunk. ----
    const int tq = tid >> 5;       // 0..7
    const int tk = tid & 31;       // 0..31

    for (int kc = 0; kc < SEQ / CK; ++kc) {
        __syncthreads();
        for (int i = tid; i < CK * DH / 4; i += NT) {
            const int e = i << 2;
            const int r = e >> 6, dd = e & 63;
            float4 v = *(const float4*)(Kb + (size_t)kc * CK * DH + e);
            *(float4*)(kvs + r * PS + dd) = v;
        }
        __syncthreads();

        float acc[4][8] = {};
#pragma unroll 2
        for (int d = 0; d < DH; d += 4) {
            float4 qv[4];
#pragma unroll
            for (int i = 0; i < 4; ++i)
                qv[i] = *(const float4*)(qs + (4 * tq + i) * PS + d);
#pragma unroll
            for (int j = 0; j < 8; ++j) {
                float4 kv = *(const float4*)(kvs + (32 * j + tk) * PS + d);
#pragma unroll
                for (int i = 0; i < 4; ++i) {
                    acc[i][j] = fmaf(qv[i].x, kv.x, acc[i][j]);
                    acc[i][j] = fmaf(qv[i].y, kv.y, acc[i][j]);
                    acc[i][j] = fmaf(qv[i].z, kv.z, acc[i][j]);
                    acc[i][j] = fmaf(qv[i].w, kv.w, acc[i][j]);
                }
            }
        }
#pragma unroll
        for (int i = 0; i < 4; ++i)
#pragma unroll
            for (int j = 0; j < 8; ++j) {
                const int kk = kc * CK + 32 * j + tk;
                float v = fmaf(acc[i][j], SCALE, mrow[kk]);
                v = fmaxf(v, -10000.0f);
                sc[(4 * tq + i) * SEQ + kk] = v;
            }
    }
    __syncthreads();

    // ---- phase 2: sparsemax (even h) / softmax (odd h), one warp per row ----
    const bool sparse = ((h & 1) == 0);
    const int warp = tid >> 5, lane = tid & 31;
    for (int r = warp; r < TQ; r += NT / 32) {
        float* row = sc + r * SEQ;
        float zr[32];
#pragma unroll
        for (int j = 0; j < 32; ++j) zr[j] = row[j * 32 + lane];
        float mx = -1e30f;
#pragma unroll
        for (int j = 0; j < 32; ++j) mx = fmaxf(mx, zr[j]);
        mx = warpMax(mx);

        if (sparse) {
            // Solve sum(max(z - tau, 0)) = 1 for tau in [mx - 1, mx].
            float lo = mx - 1.0f, hi = mx;
            for (int it = 0; it < 26; ++it) {
                const float tau = 0.5f * (lo + hi);
                float s = 0.f;
#pragma unroll
                for (int j = 0; j < 32; ++j) s += fmaxf(zr[j] - tau, 0.f);
                s = warpSum(s);
                if (s > 1.0f) lo = tau; else hi = tau;
            }
            const float tau = 0.5f * (lo + hi);
            float ssum = 0.f, cnt = 0.f;
#pragma unroll
            for (int j = 0; j < 32; ++j)
                if (zr[j] > tau) { ssum += zr[j]; cnt += 1.f; }
            ssum = warpSum(ssum);
            cnt  = warpSum(cnt);
            const float tf = (cnt >= 0.5f) ? (ssum - 1.0f) / cnt : tau;
#pragma unroll
            for (int j = 0; j < 32; ++j) row[j * 32 + lane] = fmaxf(zr[j] - tf, 0.f);
        } else {
            float s = 0.f;
#pragma unroll
            for (int j = 0; j < 32; ++j) { zr[j] = __expf(zr[j] - mx); s += zr[j]; }
            s = warpSum(s);
            const float inv = 1.0f / s;
#pragma unroll
            for (int j = 0; j < 32; ++j) row[j * 32 + lane] = zr[j] * inv;
        }
    }

    // ---- phase 3: out = weights @ V ----
    const int tx = tid & 15, ty = tid >> 4;
    const int qy = ty << 1, kx = tx << 2;
    float oacc[2][4] = {};
    for (int kc = 0; kc < SEQ / CK; ++kc) {
        __syncthreads();
        for (int i = tid; i < CK * DH / 4; i += NT) {
            const int e = i << 2;
            const int r = e >> 6, dd = e & 63;
            float4 v = *(const float4*)(Vb + (size_t)kc * CK * DH + e);
            *(float4*)(kvs + r * PS + dd) = v;
        }
        __syncthreads();
#pragma unroll 2
        for (int k = 0; k < CK; k += 4) {
            float4 w0 = *(const float4*)(sc + qy * SEQ + kc * CK + k);
            float4 w1 = *(const float4*)(sc + (qy + 1) * SEQ + kc * CK + k);
            float wa[4] = {w0.x, w0.y, w0.z, w0.w};
            float wb[4] = {w1.x, w1.y, w1.z, w1.w};
#pragma unroll
            for (int u = 0; u < 4; ++u) {
                float4 vv = *(const float4*)(kvs + (k + u) * PS + kx);
                oacc[0][0] = fmaf(wa[u], vv.x, oacc[0][0]);
                oacc[0][1] = fmaf(wa[u], vv.y, oacc[0][1]);
                oacc[0][2] = fmaf(wa[u], vv.z, oacc[0][2]);
                oacc[0][3] = fmaf(wa[u], vv.w, oacc[0][3]);
                oacc[1][0] = fmaf(wb[u], vv.x, oacc[1][0]);
                oacc[1][1] = fmaf(wb[u], vv.y, oacc[1][1]);
                oacc[1][2] = fmaf(wb[u], vv.z, oacc[1][2]);
                oacc[1][3] = fmaf(wb[u], vv.w, oacc[1][3]);
            }
        }
    }

    // write [B, S, H*HD]
    float* op = out + ((size_t)(b * SEQ + q0 + qy)) * DM + h * DH + kx;
    *(float4*)op        = make_float4(oacc[0][0], oacc[0][1], oacc[0][2], oacc[0][3]);
    *(float4*)(op + DM) = make_float4(oacc[1][0], oacc[1][1], oacc[1][2], oacc[1][3]);
}

// ---------------------------------------------------------------------------
extern "C" void kernel_launch(void* const* d_in, const int* in_sizes, int n_in,
                              void* d_out, int out_size) {
    const float* X    = (const float*)d_in[0];
    const float* Wq   = (const float*)d_in[1];
    const float* bq   = (const float*)d_in[2];
    const float* Wk   = (const float*)d_in[3];
    const float* bk   = (const float*)d_in[4];
    const float* Wv   = (const float*)d_in[5];
    const float* bv   = (const float*)d_in[6];
    const float* mask = (const float*)d_in[7];
    float* out = (float*)d_out;

    dim3 gp(DM / 64, MROWS / 64, 3);
    qkv_proj_kernel<<<gp, 256>>>(X, Wq, bq, Wk, bk, Wv, bv);

    cudaFuncSetAttribute(attn_kernel, cudaFuncAttributeMaxDynamicSharedMemorySize,
                         SMEM_FLOATS * (int)sizeof(float));
    dim3 ga(SEQ / TQ, NH, NB);
    attn_kernel<<<ga, NT, SMEM_FLOATS * sizeof(float)>>>(mask, out);
}

// round 4
// speedup vs baseline: 1.9016x; 1.1248x over previous
#include <cuda_runtime.h>

// Problem constants
#define NB   4
#define SEQ  1024
#define NH   16
#define DH   64
#define DM   1024
#define MROWS (NB * SEQ)

// Scratch for Q/K/V in [B, H, S, HD] layout.
__device__ float g_q[NB * NH * SEQ * DH];
__device__ float g_k[NB * NH * SEQ * DH];
__device__ float g_v[NB * NH * SEQ * DH];

__device__ __forceinline__ float to_tf32(float x) {
    unsigned u;
    asm("cvt.rna.tf32.f32 %0, %1;" : "=r"(u) : "f"(x));
    return __uint_as_float(u);
}

// Error-free-ish split: x = hi + lo with hi = tf32(x), lo = tf32(x - hi).
__device__ __forceinline__ void split_tf32(float x, float& hi, float& lo) {
    hi = to_tf32(x);
    lo = to_tf32(x - hi);
}

// D = A(16x8 tf32, row) @ B(8x8 tf32, col) + C, fp32 accumulate, in-place.
__device__ __forceinline__ void mma_tf32(float* c, const unsigned* a, const unsigned* b) {
    asm volatile(
        "mma.sync.aligned.m16n8k8.row.col.f32.tf32.tf32.f32 "
        "{%0,%1,%2,%3},{%4,%5,%6,%7},{%8,%9},{%0,%1,%2,%3};"
        : "+f"(c[0]), "+f"(c[1]), "+f"(c[2]), "+f"(c[3])
        : "r"(a[0]), "r"(a[1]), "r"(a[2]), "r"(a[3]), "r"(b[0]), "r"(b[1]));
}

// 3xTF32: c += ah*bh + al*bh + ah*bl
__device__ __forceinline__ void mma3(float* c, const unsigned* ah, const unsigned* al,
                                     const unsigned* bh, const unsigned* bl) {
    mma_tf32(c, ah, bh);
    mma_tf32(c, al, bh);
    mma_tf32(c, ah, bl);
}

__device__ __forceinline__ float warpMax(float v) {
#pragma unroll
    for (int o = 16; o > 0; o >>= 1) v = fmaxf(v, __shfl_xor_sync(0xffffffffu, v, o));
    return v;
}
__device__ __forceinline__ float warpSum(float v) {
#pragma unroll
    for (int o = 16; o > 0; o >>= 1) v += __shfl_xor_sync(0xffffffffu, v, o);
    return v;
}

// ---------------------------------------------------------------------------
// QKV projection, 3xTF32. CTA tile 128x128, k-stage 32, 8 warps (2x4),
// warp tile 64x32. hi/lo tiles staged in dynamic SMEM. blockIdx.z = q/k/v.
// ---------------------------------------------------------------------------
constexpr int PXS = 36;    // Xs row stride   (a-frag banks: 4g+t, unique)
constexpr int PWS = 136;   // Ws row stride   (b-frag banks: 8t+g, unique)
constexpr int PROJ_SMEM_FLOATS = 2 * 128 * PXS + 2 * 32 * PWS;

__global__ __launch_bounds__(256) void qkv_proj_tc(
    const float* __restrict__ X,
    const float* __restrict__ Wq, const float* __restrict__ bq,
    const float* __restrict__ Wk, const float* __restrict__ bk,
    const float* __restrict__ Wv, const float* __restrict__ bv) {
    extern __shared__ float psm[];
    float* Xh = psm;                    // [128][PXS]
    float* Xl = Xh + 128 * PXS;
    float* Wh = Xl + 128 * PXS;         // [32][PWS]
    float* Wl = Wh + 32 * PWS;

    const float* W;
    const float* bias;
    float* outp;
    if (blockIdx.z == 0)      { W = Wq; bias = bq; outp = g_q; }
    else if (blockIdx.z == 1) { W = Wk; bias = bk; outp = g_k; }
    else                      { W = Wv; bias = bv; outp = g_v; }

    const int tid = threadIdx.x;
    const int warp = tid >> 5, lane = tid & 31;
    const int g = lane >> 2, t = lane & 3;
    const int wm = (warp >> 2) * 64, wn = (warp & 3) * 32;
    const int m0 = blockIdx.y * 128, n0 = blockIdx.x * 128;

    float acc[4][4][4] = {};

    for (int k0 = 0; k0 < DM; k0 += 32) {
        __syncthreads();
#pragma unroll
        for (int it = 0; it < 4; ++it) {
            const int idx = tid + 256 * it;
            const int r = idx >> 3, c4 = (idx & 7) << 2;
            float4 v = *(const float4*)(X + (size_t)(m0 + r) * DM + k0 + c4);
            float4 hv, lv;
            split_tf32(v.x, hv.x, lv.x); split_tf32(v.y, hv.y, lv.y);
            split_tf32(v.z, hv.z, lv.z); split_tf32(v.w, hv.w, lv.w);
            *(float4*)(Xh + r * PXS + c4) = hv;
            *(float4*)(Xl + r * PXS + c4) = lv;
        }
#pragma unroll
        for (int it = 0; it < 4; ++it) {
            const int idx = tid + 256 * it;
            const int r = idx >> 5, c4 = (idx & 31) << 2;
            float4 v = *(const float4*)(W + (size_t)(k0 + r) * DM + n0 + c4);
            float4 hv, lv;
            split_tf32(v.x, hv.x, lv.x); split_tf32(v.y, hv.y, lv.y);
            split_tf32(v.z, hv.z, lv.z); split_tf32(v.w, hv.w, lv.w);
            *(float4*)(Wh + r * PWS + c4) = hv;
            *(float4*)(Wl + r * PWS + c4) = lv;
        }
        __syncthreads();

#pragma unroll
        for (int ks = 0; ks < 4; ++ks) {
            unsigned ah[4][4], al[4][4], bh[4][2], bl[4][2];
#pragma unroll
            for (int i = 0; i < 4; ++i) {
                const int off = (wm + 16 * i + g) * PXS + 8 * ks + t;
                ah[i][0] = __float_as_uint(Xh[off]);
                ah[i][1] = __float_as_uint(Xh[off + 8 * PXS]);
                ah[i][2] = __float_as_uint(Xh[off + 4]);
                ah[i][3] = __float_as_uint(Xh[off + 8 * PXS + 4]);
                al[i][0] = __float_as_uint(Xl[off]);
                al[i][1] = __float_as_uint(Xl[off + 8 * PXS]);
                al[i][2] = __float_as_uint(Xl[off + 4]);
                al[i][3] = __float_as_uint(Xl[off + 8 * PXS + 4]);
            }
#pragma unroll
            for (int j = 0; j < 4; ++j) {
                const int off = (8 * ks + t) * PWS + wn + 8 * j + g;
                bh[j][0] = __float_as_uint(Wh[off]);
                bh[j][1] = __float_as_uint(Wh[off + 4 * PWS]);
                bl[j][0] = __float_as_uint(Wl[off]);
                bl[j][1] = __float_as_uint(Wl[off + 4 * PWS]);
            }
#pragma unroll
            for (int i = 0; i < 4; ++i)
#pragma unroll
                for (int j = 0; j < 4; ++j)
                    mma3(acc[i][j], ah[i], al[i], bh[j], bl[j]);
        }
    }

    // epilogue: + bias, scatter to [B,H,S,HD]
#pragma unroll
    for (int j = 0; j < 4; ++j) {
        const int n = n0 + wn + 8 * j + 2 * t;
        const float b0v = bias[n], b1v = bias[n + 1];
        const int h = n >> 6, hd = n & 63;
#pragma unroll
        for (int i = 0; i < 4; ++i) {
            const int m = m0 + wm + 16 * i + g;
            const int bI = m >> 10, s = m & 1023;
            float* p = outp + ((size_t)((bI * NH + h) * SEQ + s)) * DH + hd;
            *(float2*)p = make_float2(acc[i][j][0] + b0v, acc[i][j][1] + b1v);
            const int m2 = m + 8;
            const int bI2 = m2 >> 10, s2 = m2 & 1023;
            float* p2 = outp + ((size_t)((bI2 * NH + h) * SEQ + s2)) * DH + hd;
            *(float2*)p2 = make_float2(acc[i][j][2] + b0v, acc[i][j][3] + b1v);
        }
    }
}

// ---------------------------------------------------------------------------
// Attention, 3xTF32. One CTA per (b, h, 32-q tile). Scores (fp32) in SMEM.
//   phase 1: scores = clamp(QK^T*scale + mask, -1e4)   via 3xTF32 MMA
//   phase 2: sparsemax (even h) / softmax (odd h), full fp32
//   phase 3: out = weights @ V, weights split in registers, V hi/lo in SMEM
// ---------------------------------------------------------------------------
constexpr int TQ = 32;
constexpr int CK = 128;
constexpr int NT = 256;
constexpr int PS = 72;            // q/kv stride: a-frag 8g+t unique, b-frag 8t+g unique
constexpr int SCP = 1028;         // score row stride (4g+t unique)
constexpr int ATTN_SMEM_FLOATS = TQ * SCP + 2 * TQ * PS + 2 * CK * PS;
constexpr float SCALE = 0.125f;

__global__ __launch_bounds__(NT) void attn_tc(const float* __restrict__ mask,
                                              float* __restrict__ out) {
    extern __shared__ float sm[];
    float* sc = sm;                   // [TQ][SCP]  fp32 scores/weights
    float* qh = sm + TQ * SCP;        // [TQ][PS]
    float* ql = qh + TQ * PS;
    float* kh = ql + TQ * PS;         // [CK][PS]
    float* kl = kh + CK * PS;

    const int tid = threadIdx.x;
    const int b = blockIdx.z, h = blockIdx.y;
    const int q0 = blockIdx.x * TQ;
    const int bh_i = b * NH + h;
    const float* Qb = g_q + ((size_t)bh_i * SEQ + q0) * DH;
    const float* Kb = g_k + (size_t)bh_i * SEQ * DH;
    const float* Vb = g_v + (size_t)bh_i * SEQ * DH;
    const float* mrow = mask + b * SEQ;

    const int warp = tid >> 5, lane = tid & 31;
    const int g = lane >> 2, t = lane & 3;

    // q tile -> smem hi/lo
    for (int i = tid; i < TQ * DH / 4; i += NT) {
        const int e = i << 2;
        const int qi = e >> 6, dd = e & 63;
        float4 v = *(const float4*)(Qb + e);
        float4 hv, lv;
        split_tf32(v.x, hv.x, lv.x); split_tf32(v.y, hv.y, lv.y);
        split_tf32(v.z, hv.z, lv.z); split_tf32(v.w, hv.w, lv.w);
        *(float4*)(qh + qi * PS + dd) = hv;
        *(float4*)(ql + qi * PS + dd) = lv;
    }

    // ---- phase 1: scores. warp owns 16 k-cols per 128-chunk ----
    for (int kc = 0; kc < SEQ / CK; ++kc) {
        __syncthreads();
        for (int i = tid; i < CK * DH / 4; i += NT) {
            const int e = i << 2;
            const int r = e >> 6, dd = e & 63;
            float4 v = *(const float4*)(Kb + (size_t)kc * CK * DH + e);
            float4 hv, lv;
            split_tf32(v.x, hv.x, lv.x); split_tf32(v.y, hv.y, lv.y);
            split_tf32(v.z, hv.z, lv.z); split_tf32(v.w, hv.w, lv.w);
            *(float4*)(kh + r * PS + dd) = hv;
            *(float4*)(kl + r * PS + dd) = lv;
        }
        __syncthreads();

        float acc[2][2][4] = {};
#pragma unroll
        for (int ks = 0; ks < 8; ++ks) {
            unsigned ah[2][4], al[2][4], bhf[2][2], blf[2][2];
#pragma unroll
            for (int i = 0; i < 2; ++i) {
                const int off = (16 * i + g) * PS + 8 * ks + t;
                ah[i][0] = __float_as_uint(qh[off]);
                ah[i][1] = __float_as_uint(qh[off + 8 * PS]);
                ah[i][2] = __float_as_uint(qh[off + 4]);
                ah[i][3] = __float_as_uint(qh[off + 8 * PS + 4]);
                al[i][0] = __float_as_uint(ql[off]);
                al[i][1] = __float_as_uint(ql[off + 8 * PS]);
                al[i][2] = __float_as_uint(ql[off + 4]);
                al[i][3] = __float_as_uint(ql[off + 8 * PS + 4]);
            }
#pragma unroll
            for (int j = 0; j < 2; ++j) {
                const int off = (warp * 16 + 8 * j + g) * PS + 8 * ks + t;
                bhf[j][0] = __float_as_uint(kh[off]);
                bhf[j][1] = __float_as_uint(kh[off + 4]);
                blf[j][0] = __float_as_uint(kl[off]);
                blf[j][1] = __float_as_uint(kl[off + 4]);
            }
#pragma unroll
            for (int i = 0; i < 2; ++i)
#pragma unroll
                for (int j = 0; j < 2; ++j)
                    mma3(acc[i][j], ah[i], al[i], bhf[j], blf[j]);
        }
#pragma unroll
        for (int j = 0; j < 2; ++j) {
            const int s = kc * CK + warp * 16 + 8 * j + 2 * t;
            const float m0v = mrow[s], m1v = mrow[s + 1];
#pragma unroll
            for (int i = 0; i < 2; ++i) {
                const int q = 16 * i + g;
                float v0 = fmaxf(fmaf(acc[i][j][0], SCALE, m0v), -10000.0f);
                float v1 = fmaxf(fmaf(acc[i][j][1], SCALE, m1v), -10000.0f);
                *(float2*)(sc + q * SCP + s) = make_float2(v0, v1);
                float v2 = fmaxf(fmaf(acc[i][j][2], SCALE, m0v), -10000.0f);
                float v3 = fmaxf(fmaf(acc[i][j][3], SCALE, m1v), -10000.0f);
                *(float2*)(sc + (q + 8) * SCP + s) = make_float2(v2, v3);
            }
        }
    }
    __syncthreads();

    // ---- phase 2: sparsemax / softmax (fp32) ----
    const bool sparse = ((h & 1) == 0);
    for (int r = warp; r < TQ; r += NT / 32) {
        float* row = sc + r * SCP;
        float zr[32];
#pragma unroll
        for (int j = 0; j < 32; ++j) zr[j] = row[j * 32 + lane];
        float mx = -1e30f;
#pragma unroll
        for (int j = 0; j < 32; ++j) mx = fmaxf(mx, zr[j]);
        mx = warpMax(mx);

        if (sparse) {
            float lo = mx - 1.0f, hi = mx;
            for (int it = 0; it < 26; ++it) {
                const float tau = 0.5f * (lo + hi);
                float s = 0.f;
#pragma unroll
                for (int j = 0; j < 32; ++j) s += fmaxf(zr[j] - tau, 0.f);
                s = warpSum(s);
                if (s > 1.0f) lo = tau; else hi = tau;
            }
            const float tau = 0.5f * (lo + hi);
            float ssum = 0.f, cnt = 0.f;
#pragma unroll
            for (int j = 0; j < 32; ++j)
                if (zr[j] > tau) { ssum += zr[j]; cnt += 1.f; }
            ssum = warpSum(ssum);
            cnt  = warpSum(cnt);
            const float tf = (cnt >= 0.5f) ? (ssum - 1.0f) / cnt : tau;
#pragma unroll
            for (int j = 0; j < 32; ++j) row[j * 32 + lane] = fmaxf(zr[j] - tf, 0.f);
        } else {
            float s = 0.f;
#pragma unroll
            for (int j = 0; j < 32; ++j) { zr[j] = __expf(zr[j] - mx); s += zr[j]; }
            s = warpSum(s);
            const float inv = 1.0f / s;
#pragma unroll
            for (int j = 0; j < 32; ++j) row[j * 32 + lane] = zr[j] * inv;
        }
    }

    // ---- phase 3: out = weights @ V (warp owns 8 output dims) ----
    float oacc[2][4] = {};
    for (int kc = 0; kc < SEQ / CK; ++kc) {
        __syncthreads();
        for (int i = tid; i < CK * DH / 4; i += NT) {
            const int e = i << 2;
            const int r = e >> 6, dd = e & 63;
            float4 v = *(const float4*)(Vb + (size_t)kc * CK * DH + e);
            float4 hv, lv;
            split_tf32(v.x, hv.x, lv.x); split_tf32(v.y, hv.y, lv.y);
            split_tf32(v.z, hv.z, lv.z); split_tf32(v.w, hv.w, lv.w);
            *(float4*)(kh + r * PS + dd) = hv;
            *(float4*)(kl + r * PS + dd) = lv;
        }
        __syncthreads();
#pragma unroll 2
        for (int kk = 0; kk < CK / 8; ++kk) {
            unsigned ah[2][4], al[2][4], bhf[2], blf[2];
#pragma unroll
            for (int i = 0; i < 2; ++i) {
                const float* ap = sc + (16 * i + g) * SCP + kc * CK + 8 * kk + t;
                float w0 = ap[0], w1 = ap[8 * SCP], w2 = ap[4], w3 = ap[8 * SCP + 4];
                float hv, lv;
                split_tf32(w0, hv, lv); ah[i][0] = __float_as_uint(hv); al[i][0] = __float_as_uint(lv);
                split_tf32(w1, hv, lv); ah[i][1] = __float_as_uint(hv); al[i][1] = __float_as_uint(lv);
                split_tf32(w2, hv, lv); ah[i][2] = __float_as_uint(hv); al[i][2] = __float_as_uint(lv);
                split_tf32(w3, hv, lv); ah[i][3] = __float_as_uint(hv); al[i][3] = __float_as_uint(lv);
            }
            const int off = (8 * kk + t) * PS + 8 * warp + g;
            bhf[0] = __float_as_uint(kh[off]);
            bhf[1] = __float_as_uint(kh[off + 4 * PS]);
            blf[0] = __float_as_uint(kl[off]);
            blf[1] = __float_as_uint(kl[off + 4 * PS]);
            mma3(oacc[0], ah[0], al[0], bhf, blf);
            mma3(oacc[1], ah[1], al[1], bhf, blf);
        }
    }

    // write [B, S, H*HD]
#pragma unroll
    for (int i = 0; i < 2; ++i) {
        const int q = q0 + 16 * i + g;
        float* p = out + (size_t)(b * SEQ + q) * DM + h * DH + 8 * warp + 2 * t;
        *(float2*)p = make_float2(oacc[i][0], oacc[i][1]);
        *(float2*)(p + 8 * DM) = make_float2(oacc[i][2], oacc[i][3]);
    }
}

// ---------------------------------------------------------------------------
extern "C" void kernel_launch(void* const* d_in, const int* in_sizes, int n_in,
                              void* d_out, int out_size) {
    const float* X    = (const float*)d_in[0];
    const float* Wq   = (const float*)d_in[1];
    const float* bq   = (const float*)d_in[2];
    const float* Wk   = (const float*)d_in[3];
    const float* bk   = (const float*)d_in[4];
    const float* Wv   = (const float*)d_in[5];
    const float* bv   = (const float*)d_in[6];
    const float* mask = (const float*)d_in[7];
    float* out = (float*)d_out;

    cudaFuncSetAttribute(qkv_proj_tc, cudaFuncAttributeMaxDynamicSharedMemorySize,
                         PROJ_SMEM_FLOATS * (int)sizeof(float));
    dim3 gp(DM / 128, MROWS / 128, 3);
    qkv_proj_tc<<<gp, 256, PROJ_SMEM_FLOATS * sizeof(float)>>>(X, Wq, bq, Wk, bk, Wv, bv);

    cudaFuncSetAttribute(attn_tc, cudaFuncAttributeMaxDynamicSharedMemorySize,
                         ATTN_SMEM_FLOATS * (int)sizeof(float));
    dim3 ga(SEQ / TQ, NH, NB);
    attn_tc<<<ga, NT, ATTN_SMEM_FLOATS * sizeof(float)>>>(mask, out);
}

// round 5
// speedup vs baseline: 2.2755x; 1.1966x over previous
#include <cuda_runtime.h>

// Problem constants
#define NB   4
#define SEQ  1024
#define NH   16
#define DH   64
#define DM   1024
#define MROWS (NB * SEQ)

// Scratch for Q/K/V in [B, H, S, HD] layout.
__device__ float g_q[NB * NH * SEQ * DH];
__device__ float g_k[NB * NH * SEQ * DH];
__device__ float g_v[NB * NH * SEQ * DH];

__device__ __forceinline__ float to_tf32(float x) {
    unsigned u;
    asm("cvt.rna.tf32.f32 %0, %1;" : "=r"(u) : "f"(x));
    return __uint_as_float(u);
}
__device__ __forceinline__ void split_tf32(float x, float& hi, float& lo) {
    hi = to_tf32(x);
    lo = to_tf32(x - hi);
}
__device__ __forceinline__ void mma_tf32(float* c, const unsigned* a, const unsigned* b) {
    asm volatile(
        "mma.sync.aligned.m16n8k8.row.col.f32.tf32.tf32.f32 "
        "{%0,%1,%2,%3},{%4,%5,%6,%7},{%8,%9},{%0,%1,%2,%3};"
        : "+f"(c[0]), "+f"(c[1]), "+f"(c[2]), "+f"(c[3])
        : "r"(a[0]), "r"(a[1]), "r"(a[2]), "r"(a[3]), "r"(b[0]), "r"(b[1]));
}
__device__ __forceinline__ void mma3(float* c, const unsigned* ah, const unsigned* al,
                                     const unsigned* bh, const unsigned* bl) {
    mma_tf32(c, ah, bh);
    mma_tf32(c, al, bh);
    mma_tf32(c, ah, bl);
}

__device__ __forceinline__ float warpMax(float v) {
#pragma unroll
    for (int o = 16; o > 0; o >>= 1) v = fmaxf(v, __shfl_xor_sync(0xffffffffu, v, o));
    return v;
}
__device__ __forceinline__ float warpSum(float v) {
#pragma unroll
    for (int o = 16; o > 0; o >>= 1) v += __shfl_xor_sync(0xffffffffu, v, o);
    return v;
}

// ---------------------------------------------------------------------------
// QKV projection, 3xTF32 (unchanged from R4 — it is correct and not the
// current bottleneck). CTA 128x128, k-stage 32, 8 warps, warp tile 64x32.
// ---------------------------------------------------------------------------
constexpr int PXS = 36;    // ≡4 mod 32: a-frag banks 4g+t unique
constexpr int PWS = 136;   // ≡8 mod 32: b-frag banks 8t+g unique
constexpr int PROJ_SMEM_FLOATS = 2 * 128 * PXS + 2 * 32 * PWS;

__global__ __launch_bounds__(256) void qkv_proj_tc(
    const float* __restrict__ X,
    const float* __restrict__ Wq, const float* __restrict__ bq,
    const float* __restrict__ Wk, const float* __restrict__ bk,
    const float* __restrict__ Wv, const float* __restrict__ bv) {
    extern __shared__ float psm[];
    float* Xh = psm;
    float* Xl = Xh + 128 * PXS;
    float* Wh = Xl + 128 * PXS;
    float* Wl = Wh + 32 * PWS;

    const float* W;
    const float* bias;
    float* outp;
    if (blockIdx.z == 0)      { W = Wq; bias = bq; outp = g_q; }
    else if (blockIdx.z == 1) { W = Wk; bias = bk; outp = g_k; }
    else                      { W = Wv; bias = bv; outp = g_v; }

    const int tid = threadIdx.x;
    const int warp = tid >> 5, lane = tid & 31;
    const int g = lane >> 2, t = lane & 3;
    const int wm = (warp >> 2) * 64, wn = (warp & 3) * 32;
    const int m0 = blockIdx.y * 128, n0 = blockIdx.x * 128;

    float acc[4][4][4] = {};

    for (int k0 = 0; k0 < DM; k0 += 32) {
        __syncthreads();
#pragma unroll
        for (int it = 0; it < 4; ++it) {
            const int idx = tid + 256 * it;
            const int r = idx >> 3, c4 = (idx & 7) << 2;
            float4 v = *(const float4*)(X + (size_t)(m0 + r) * DM + k0 + c4);
            float4 hv, lv;
            split_tf32(v.x, hv.x, lv.x); split_tf32(v.y, hv.y, lv.y);
            split_tf32(v.z, hv.z, lv.z); split_tf32(v.w, hv.w, lv.w);
            *(float4*)(Xh + r * PXS + c4) = hv;
            *(float4*)(Xl + r * PXS + c4) = lv;
        }
#pragma unroll
        for (int it = 0; it < 4; ++it) {
            const int idx = tid + 256 * it;
            const int r = idx >> 5, c4 = (idx & 31) << 2;
            float4 v = *(const float4*)(W + (size_t)(k0 + r) * DM + n0 + c4);
            float4 hv, lv;
            split_tf32(v.x, hv.x, lv.x); split_tf32(v.y, hv.y, lv.y);
            split_tf32(v.z, hv.z, lv.z); split_tf32(v.w, hv.w, lv.w);
            *(float4*)(Wh + r * PWS + c4) = hv;
            *(float4*)(Wl + r * PWS + c4) = lv;
        }
        __syncthreads();

#pragma unroll
        for (int ks = 0; ks < 4; ++ks) {
            unsigned ah[4][4], al[4][4], bh[4][2], bl[4][2];
#pragma unroll
            for (int i = 0; i < 4; ++i) {
                const int off = (wm + 16 * i + g) * PXS + 8 * ks + t;
                ah[i][0] = __float_as_uint(Xh[off]);
                ah[i][1] = __float_as_uint(Xh[off + 8 * PXS]);
                ah[i][2] = __float_as_uint(Xh[off + 4]);
                ah[i][3] = __float_as_uint(Xh[off + 8 * PXS + 4]);
                al[i][0] = __float_as_uint(Xl[off]);
                al[i][1] = __float_as_uint(Xl[off + 8 * PXS]);
                al[i][2] = __float_as_uint(Xl[off + 4]);
                al[i][3] = __float_as_uint(Xl[off + 8 * PXS + 4]);
            }
#pragma unroll
            for (int j = 0; j < 4; ++j) {
                const int off = (8 * ks + t) * PWS + wn + 8 * j + g;
                bh[j][0] = __float_as_uint(Wh[off]);
                bh[j][1] = __float_as_uint(Wh[off + 4 * PWS]);
                bl[j][0] = __float_as_uint(Wl[off]);
                bl[j][1] = __float_as_uint(Wl[off + 4 * PWS]);
            }
#pragma unroll
            for (int i = 0; i < 4; ++i)
#pragma unroll
                for (int j = 0; j < 4; ++j)
                    mma3(acc[i][j], ah[i], al[i], bh[j], bl[j]);
        }
    }

#pragma unroll
    for (int j = 0; j < 4; ++j) {
        const int n = n0 + wn + 8 * j + 2 * t;
        const float b0v = bias[n], b1v = bias[n + 1];
        const int h = n >> 6, hd = n & 63;
#pragma unroll
        for (int i = 0; i < 4; ++i) {
            const int m = m0 + wm + 16 * i + g;
            const int bI = m >> 10, s = m & 1023;
            float* p = outp + ((size_t)((bI * NH + h) * SEQ + s)) * DH + hd;
            *(float2*)p = make_float2(acc[i][j][0] + b0v, acc[i][j][1] + b1v);
            const int m2 = m + 8;
            const int bI2 = m2 >> 10, s2 = m2 & 1023;
            float* p2 = outp + ((size_t)((bI2 * NH + h) * SEQ + s2)) * DH + hd;
            *(float2*)p2 = make_float2(acc[i][j][2] + b0v, acc[i][j][3] + b1v);
        }
    }
}

// ---------------------------------------------------------------------------
// Attention, 3xTF32, 512 threads (16 warps), register-prefetched staging.
//   phase 1: warp (wq,wk) computes 16q x 16k per 128-chunk
//   phase 2: each warp does 2 independent rows (ILP) of sparsemax/softmax
//   phase 3: warp (wq,wd) computes 16q x 8 output dims
// Strides: q/K buffers 68 (≡4 mod 32), V buffer 72 (≡8 mod 32), sc 1028 (≡4).
// ---------------------------------------------------------------------------
constexpr int TQ  = 32;
constexpr int CK  = 128;
constexpr int NCH = SEQ / CK;     // 8
constexpr int NT  = 512;
constexpr int PSQ = 68;
constexpr int PSV = 72;           // kv buffer allocated at this stride
constexpr int SCP = 1028;
constexpr int ATTN_SMEM_FLOATS = TQ * SCP + 2 * TQ * PSQ + 2 * CK * PSV;
constexpr float SCALE = 0.125f;

__global__ __launch_bounds__(NT, 1) void attn_tc(const float* __restrict__ mask,
                                                 float* __restrict__ out) {
    extern __shared__ float sm[];
    float* sc = sm;                   // [TQ][SCP]
    float* qh = sm + TQ * SCP;        // [TQ][PSQ]
    float* ql = qh + TQ * PSQ;
    float* kh = ql + TQ * PSQ;        // [CK][PSV] (stride 68 used in phase 1)
    float* kl = kh + CK * PSV;

    const int tid = threadIdx.x;
    const int b = blockIdx.z, h = blockIdx.y;
    const int q0 = blockIdx.x * TQ;
    const int bh_i = b * NH + h;
    const float* Qb = g_q + ((size_t)bh_i * SEQ + q0) * DH;
    const float* Kb = g_k + (size_t)bh_i * SEQ * DH;
    const float* Vb = g_v + (size_t)bh_i * SEQ * DH;
    const float* mrow = mask + b * SEQ;

    const int warp = tid >> 5, lane = tid & 31;
    const int g = lane >> 2, t = lane & 3;
    const int wq = warp >> 3;         // 0..1
    const int wk = warp & 7;          // 0..7 (k-cols in ph1, out-dims in ph3)

    // q tile -> smem hi/lo (512 threads: exactly one float4 each)
    {
        const int e = tid << 2;
        const int qi = e >> 6, dd = e & 63;
        float4 v = *(const float4*)(Qb + e);
        float4 hv, lv;
        split_tf32(v.x, hv.x, lv.x); split_tf32(v.y, hv.y, lv.y);
        split_tf32(v.z, hv.z, lv.z); split_tf32(v.w, hv.w, lv.w);
        *(float4*)(qh + qi * PSQ + dd) = hv;
        *(float4*)(ql + qi * PSQ + dd) = lv;
    }
    // stage K chunk 0 (stride 68)
#pragma unroll
    for (int it = 0; it < 4; ++it) {
        const int e = (tid + NT * it) << 2;
        const int r = e >> 6, dd = e & 63;
        float4 v = *(const float4*)(Kb + e);
        float4 hv, lv;
        split_tf32(v.x, hv.x, lv.x); split_tf32(v.y, hv.y, lv.y);
        split_tf32(v.z, hv.z, lv.z); split_tf32(v.w, hv.w, lv.w);
        *(float4*)(kh + r * PSQ + dd) = hv;
        *(float4*)(kl + r * PSQ + dd) = lv;
    }

    // ---- phase 1: scores ----
    for (int kc = 0; kc < NCH; ++kc) {
        __syncthreads();
        float4 pf[4];
        const bool more = (kc + 1 < NCH);
        if (more) {
#pragma unroll
            for (int it = 0; it < 4; ++it) {
                const int e = (tid + NT * it) << 2;
                pf[it] = *(const float4*)(Kb + (size_t)(kc + 1) * CK * DH + e);
            }
        }

        float acc[2][4] = {};
#pragma unroll
        for (int ks = 0; ks < 8; ++ks) {
            unsigned ah[4], al[4], bhf[2][2], blf[2][2];
            const int aoff = (16 * wq + g) * PSQ + 8 * ks + t;
            ah[0] = __float_as_uint(qh[aoff]);
            ah[1] = __float_as_uint(qh[aoff + 8 * PSQ]);
            ah[2] = __float_as_uint(qh[aoff + 4]);
            ah[3] = __float_as_uint(qh[aoff + 8 * PSQ + 4]);
            al[0] = __float_as_uint(ql[aoff]);
            al[1] = __float_as_uint(ql[aoff + 8 * PSQ]);
            al[2] = __float_as_uint(ql[aoff + 4]);
            al[3] = __float_as_uint(ql[aoff + 8 * PSQ + 4]);
#pragma unroll
            for (int j = 0; j < 2; ++j) {
                const int boff = (16 * wk + 8 * j + g) * PSQ + 8 * ks + t;
                bhf[j][0] = __float_as_uint(kh[boff]);
                bhf[j][1] = __float_as_uint(kh[boff + 4]);
                blf[j][0] = __float_as_uint(kl[boff]);
                blf[j][1] = __float_as_uint(kl[boff + 4]);
            }
            mma3(acc[0], ah, al, bhf[0], blf[0]);
            mma3(acc[1], ah, al, bhf[1], blf[1]);
        }
#pragma unroll
        for (int j = 0; j < 2; ++j) {
            const int s = kc * CK + 16 * wk + 8 * j + 2 * t;
            const float2 mv = *(const float2*)(mrow + s);
            const int q = 16 * wq + g;
            float v0 = fmaxf(fmaf(acc[j][0], SCALE, mv.x), -10000.0f);
            float v1 = fmaxf(fmaf(acc[j][1], SCALE, mv.y), -10000.0f);
            *(float2*)(sc + q * SCP + s) = make_float2(v0, v1);
            float v2 = fmaxf(fmaf(acc[j][2], SCALE, mv.x), -10000.0f);
            float v3 = fmaxf(fmaf(acc[j][3], SCALE, mv.y), -10000.0f);
            *(float2*)(sc + (q + 8) * SCP + s) = make_float2(v2, v3);
        }

        __syncthreads();
        if (more) {
#pragma unroll
            for (int it = 0; it < 4; ++it) {
                const int e = (tid + NT * it) << 2;
                const int r = e >> 6, dd = e & 63;
                float4 hv, lv;
                split_tf32(pf[it].x, hv.x, lv.x); split_tf32(pf[it].y, hv.y, lv.y);
                split_tf32(pf[it].z, hv.z, lv.z); split_tf32(pf[it].w, hv.w, lv.w);
                *(float4*)(kh + r * PSQ + dd) = hv;
                *(float4*)(kl + r * PSQ + dd) = lv;
            }
        }
    }
    __syncthreads();

    // ---- phase 2: sparsemax / softmax, two independent rows per warp ----
    {
        const bool sparse = ((h & 1) == 0);
        float* row0 = sc + warp * SCP;
        float* row1 = sc + (warp + 16) * SCP;
        float z0[32], z1[32];
#pragma unroll
        for (int j = 0; j < 32; ++j) { z0[j] = row0[j * 32 + lane]; z1[j] = row1[j * 32 + lane]; }
        float mx0 = -1e30f, mx1 = -1e30f;
#pragma unroll
        for (int j = 0; j < 32; ++j) { mx0 = fmaxf(mx0, z0[j]); mx1 = fmaxf(mx1, z1[j]); }
        mx0 = warpMax(mx0);
        mx1 = warpMax(mx1);

        if (sparse) {
            float lo0 = mx0 - 1.0f, hi0 = mx0, lo1 = mx1 - 1.0f, hi1 = mx1;
            for (int it = 0; it < 26; ++it) {
                const float ta0 = 0.5f * (lo0 + hi0), ta1 = 0.5f * (lo1 + hi1);
                float s0 = 0.f, s1 = 0.f;
#pragma unroll
                for (int j = 0; j < 32; ++j) {
                    s0 += fmaxf(z0[j] - ta0, 0.f);
                    s1 += fmaxf(z1[j] - ta1, 0.f);
                }
                s0 = warpSum(s0);
                s1 = warpSum(s1);
                if (s0 > 1.0f) lo0 = ta0; else hi0 = ta0;
                if (s1 > 1.0f) lo1 = ta1; else hi1 = ta1;
            }
            const float ta0 = 0.5f * (lo0 + hi0), ta1 = 0.5f * (lo1 + hi1);
            float ss0 = 0.f, c0 = 0.f, ss1 = 0.f, c1 = 0.f;
#pragma unroll
            for (int j = 0; j < 32; ++j) {
                if (z0[j] > ta0) { ss0 += z0[j]; c0 += 1.f; }
                if (z1[j] > ta1) { ss1 += z1[j]; c1 += 1.f; }
            }
            ss0 = warpSum(ss0); c0 = warpSum(c0);
            ss1 = warpSum(ss1); c1 = warpSum(c1);
            const float tf0 = (c0 >= 0.5f) ? (ss0 - 1.0f) / c0 : ta0;
            const float tf1 = (c1 >= 0.5f) ? (ss1 - 1.0f) / c1 : ta1;
#pragma unroll
            for (int j = 0; j < 32; ++j) {
                row0[j * 32 + lane] = fmaxf(z0[j] - tf0, 0.f);
                row1[j * 32 + lane] = fmaxf(z1[j] - tf1, 0.f);
            }
        } else {
            float s0 = 0.f, s1 = 0.f;
#pragma unroll
            for (int j = 0; j < 32; ++j) {
                z0[j] = __expf(z0[j] - mx0); s0 += z0[j];
                z1[j] = __expf(z1[j] - mx1); s1 += z1[j];
            }
            s0 = warpSum(s0);
            s1 = warpSum(s1);
            const float i0 = 1.0f / s0, i1 = 1.0f / s1;
#pragma unroll
            for (int j = 0; j < 32; ++j) {
                row0[j * 32 + lane] = z0[j] * i0;
                row1[j * 32 + lane] = z1[j] * i1;
            }
        }
    }

    // stage V chunk 0 (stride 72); kvs untouched by phase 2, sc sync comes below
#pragma unroll
    for (int it = 0; it < 4; ++it) {
        const int e = (tid + NT * it) << 2;
        const int r = e >> 6, dd = e & 63;
        float4 v = *(const float4*)(Vb + e);
        float4 hv, lv;
        split_tf32(v.x, hv.x, lv.x); split_tf32(v.y, hv.y, lv.y);
        split_tf32(v.z, hv.z, lv.z); split_tf32(v.w, hv.w, lv.w);
        *(float4*)(kh + r * PSV + dd) = hv;
        *(float4*)(kl + r * PSV + dd) = lv;
    }

    // ---- phase 3: out = weights @ V ----
    float oacc[4] = {};
    for (int kc = 0; kc < NCH; ++kc) {
        __syncthreads();
        float4 pf[4];
        const bool more = (kc + 1 < NCH);
        if (more) {
#pragma unroll
            for (int it = 0; it < 4; ++it) {
                const int e = (tid + NT * it) << 2;
                pf[it] = *(const float4*)(Vb + (size_t)(kc + 1) * CK * DH + e);
            }
        }
#pragma unroll 2
        for (int kk = 0; kk < CK / 8; ++kk) {
            unsigned ah[4], al[4], bhf[2], blf[2];
            const float* ap = sc + (16 * wq + g) * SCP + kc * CK + 8 * kk + t;
            float hv, lv;
            split_tf32(ap[0],           hv, lv); ah[0] = __float_as_uint(hv); al[0] = __float_as_uint(lv);
            split_tf32(ap[8 * SCP],     hv, lv); ah[1] = __float_as_uint(hv); al[1] = __float_as_uint(lv);
            split_tf32(ap[4],           hv, lv); ah[2] = __float_as_uint(hv); al[2] = __float_as_uint(lv);
            split_tf32(ap[8 * SCP + 4], hv, lv); ah[3] = __float_as_uint(hv); al[3] = __float_as_uint(lv);
            const int boff = (8 * kk + t) * PSV + 8 * wk + g;
            bhf[0] = __float_as_uint(kh[boff]);
            bhf[1] = __float_as_uint(kh[boff + 4 * PSV]);
            blf[0] = __float_as_uint(kl[boff]);
            blf[1] = __float_as_uint(kl[boff + 4 * PSV]);
            mma3(oacc, ah, al, bhf, blf);
        }
        __syncthreads();
        if (more) {
#pragma unroll
            for (int it = 0; it < 4; ++it) {
                const int e = (tid + NT * it) << 2;
                const int r = e >> 6, dd = e & 63;
                float4 hv, lv;
                split_tf32(pf[it].x, hv.x, lv.x); split_tf32(pf[it].y, hv.y, lv.y);
                split_tf32(pf[it].z, hv.z, lv.z); split_tf32(pf[it].w, hv.w, lv.w);
                *(float4*)(kh + r * PSV + dd) = hv;
                *(float4*)(kl + r * PSV + dd) = lv;
            }
        }
    }

    // write [B, S, H*HD]
    {
        const int q = q0 + 16 * wq + g;
        float* p = out + (size_t)(b * SEQ + q) * DM + h * DH + 8 * wk + 2 * t;
        *(float2*)p = make_float2(oacc[0], oacc[1]);
        *(float2*)(p + 8 * DM) = make_float2(oacc[2], oacc[3]);
    }
}

// ---------------------------------------------------------------------------
extern "C" void kernel_launch(void* const* d_in, const int* in_sizes, int n_in,
                              void* d_out, int out_size) {
    const float* X    = (const float*)d_in[0];
    const float* Wq   = (const float*)d_in[1];
    const float* bq   = (const float*)d_in[2];
    const float* Wk   = (const float*)d_in[3];
    const float* bk   = (const float*)d_in[4];
    const float* Wv   = (const float*)d_in[5];
    const float* bv   = (const float*)d_in[6];
    const float* mask = (const float*)d_in[7];
    float* out = (float*)d_out;

    cudaFuncSetAttribute(qkv_proj_tc, cudaFuncAttributeMaxDynamicSharedMemorySize,
                         PROJ_SMEM_FLOATS * (int)sizeof(float));
    dim3 gp(DM / 128, MROWS / 128, 3);
    qkv_proj_tc<<<gp, 256, PROJ_SMEM_FLOATS * sizeof(float)>>>(X, Wq, bq, Wk, bk, Wv, bv);

    cudaFuncSetAttribute(attn_tc, cudaFuncAttributeMaxDynamicSharedMemorySize,
                         ATTN_SMEM_FLOATS * (int)sizeof(float));
    dim3 ga(SEQ / TQ, NH, NB);
    attn_tc<<<ga, NT, ATTN_SMEM_FLOATS * sizeof(float)>>>(mask, out);
}

// round 6
// speedup vs baseline: 2.4317x; 1.0686x over previous
#include <cuda_runtime.h>
#include <cstdint>

// Problem constants
#define NB   4
#define SEQ  1024
#define NH   16
#define DH   64
#define DM   1024
#define MROWS (NB * SEQ)

// Pre-split Q/K/V scratch (hi/lo tf32 pairs) in [B, H, S, HD] layout.
__device__ float g_qh[NB * NH * SEQ * DH];
__device__ float g_ql[NB * NH * SEQ * DH];
__device__ float g_kh[NB * NH * SEQ * DH];
__device__ float g_kl[NB * NH * SEQ * DH];
__device__ float g_vh[NB * NH * SEQ * DH];
__device__ float g_vl[NB * NH * SEQ * DH];

__device__ __forceinline__ float to_tf32(float x) {
    unsigned u;
    asm("cvt.rna.tf32.f32 %0, %1;" : "=r"(u) : "f"(x));
    return __uint_as_float(u);
}
__device__ __forceinline__ void split_tf32(float x, float& hi, float& lo) {
    hi = to_tf32(x);
    lo = to_tf32(x - hi);
}
__device__ __forceinline__ void mma_tf32(float* c, const unsigned* a, const unsigned* b) {
    asm volatile(
        "mma.sync.aligned.m16n8k8.row.col.f32.tf32.tf32.f32 "
        "{%0,%1,%2,%3},{%4,%5,%6,%7},{%8,%9},{%0,%1,%2,%3};"
        : "+f"(c[0]), "+f"(c[1]), "+f"(c[2]), "+f"(c[3])
        : "r"(a[0]), "r"(a[1]), "r"(a[2]), "r"(a[3]), "r"(b[0]), "r"(b[1]));
}
__device__ __forceinline__ void mma3(float* c, const unsigned* ah, const unsigned* al,
                                     const unsigned* bh, const unsigned* bl) {
    mma_tf32(c, ah, bh);
    mma_tf32(c, al, bh);
    mma_tf32(c, ah, bl);
}
__device__ __forceinline__ float warpMax(float v) {
#pragma unroll
    for (int o = 16; o > 0; o >>= 1) v = fmaxf(v, __shfl_xor_sync(0xffffffffu, v, o));
    return v;
}
__device__ __forceinline__ float warpSum(float v) {
#pragma unroll
    for (int o = 16; o > 0; o >>= 1) v += __shfl_xor_sync(0xffffffffu, v, o);
    return v;
}

#define CP_COMMIT() asm volatile("cp.async.commit_group;")
#define CP_WAIT(N)  asm volatile("cp.async.wait_group %0;" :: "n"(N))

// Copy one 64x64 fp32 tile pair (hi, lo) GMEM->SMEM via cp.async. 512 threads.
__device__ __forceinline__ void stage_cp(float* dh, float* dl,
                                         const float* gh, const float* gl,
                                         int tid, int stride) {
#pragma unroll
    for (int it = 0; it < 2; ++it) {
        const int idx = tid + 512 * it;
        const int r = idx >> 4, c = (idx & 15) << 2;
        const int so = r * stride + c;
        const int go = r * DH + c;
        uint32_t a1 = (uint32_t)__cvta_generic_to_shared(dh + so);
        uint32_t a2 = (uint32_t)__cvta_generic_to_shared(dl + so);
        asm volatile("cp.async.cg.shared.global [%0], [%1], 16;" :: "r"(a1), "l"(gh + go));
        asm volatile("cp.async.cg.shared.global [%0], [%1], 16;" :: "r"(a2), "l"(gl + go));
    }
}

// ---------------------------------------------------------------------------
// QKV projection, 3xTF32. CTA 128x128, k-stage 32, 8 warps, warp tile 64x32.
// Epilogue writes hi/lo split directly (consumed by attention without cvt).
// ---------------------------------------------------------------------------
constexpr int PXS = 36;    // ≡4 mod 32
constexpr int PWS = 136;   // ≡8 mod 32
constexpr int PROJ_SMEM_FLOATS = 2 * 128 * PXS + 2 * 32 * PWS;

__global__ __launch_bounds__(256) void qkv_proj_tc(
    const float* __restrict__ X,
    const float* __restrict__ Wq, const float* __restrict__ bq,
    const float* __restrict__ Wk, const float* __restrict__ bk,
    const float* __restrict__ Wv, const float* __restrict__ bv) {
    extern __shared__ float psm[];
    float* Xh = psm;
    float* Xl = Xh + 128 * PXS;
    float* Wh = Xl + 128 * PXS;
    float* Wl = Wh + 32 * PWS;

    const float* W;
    const float* bias;
    float *outh, *outl;
    if (blockIdx.z == 0)      { W = Wq; bias = bq; outh = g_qh; outl = g_ql; }
    else if (blockIdx.z == 1) { W = Wk; bias = bk; outh = g_kh; outl = g_kl; }
    else                      { W = Wv; bias = bv; outh = g_vh; outl = g_vl; }

    const int tid = threadIdx.x;
    const int warp = tid >> 5, lane = tid & 31;
    const int g = lane >> 2, t = lane & 3;
    const int wm = (warp >> 2) * 64, wn = (warp & 3) * 32;
    const int m0 = blockIdx.y * 128, n0 = blockIdx.x * 128;

    float acc[4][4][4] = {};

    for (int k0 = 0; k0 < DM; k0 += 32) {
        __syncthreads();
#pragma unroll
        for (int it = 0; it < 4; ++it) {
            const int idx = tid + 256 * it;
            const int r = idx >> 3, c4 = (idx & 7) << 2;
            float4 v = *(const float4*)(X + (size_t)(m0 + r) * DM + k0 + c4);
            float4 hv, lv;
            split_tf32(v.x, hv.x, lv.x); split_tf32(v.y, hv.y, lv.y);
            split_tf32(v.z, hv.z, lv.z); split_tf32(v.w, hv.w, lv.w);
            *(float4*)(Xh + r * PXS + c4) = hv;
            *(float4*)(Xl + r * PXS + c4) = lv;
        }
#pragma unroll
        for (int it = 0; it < 4; ++it) {
            const int idx = tid + 256 * it;
            const int r = idx >> 5, c4 = (idx & 31) << 2;
            float4 v = *(const float4*)(W + (size_t)(k0 + r) * DM + n0 + c4);
            float4 hv, lv;
            split_tf32(v.x, hv.x, lv.x); split_tf32(v.y, hv.y, lv.y);
            split_tf32(v.z, hv.z, lv.z); split_tf32(v.w, hv.w, lv.w);
            *(float4*)(Wh + r * PWS + c4) = hv;
            *(float4*)(Wl + r * PWS + c4) = lv;
        }
        __syncthreads();

#pragma unroll
        for (int ks = 0; ks < 4; ++ks) {
            unsigned ah[4][4], al[4][4], bh[4][2], bl[4][2];
#pragma unroll
            for (int i = 0; i < 4; ++i) {
                const int off = (wm + 16 * i + g) * PXS + 8 * ks + t;
                ah[i][0] = __float_as_uint(Xh[off]);
                ah[i][1] = __float_as_uint(Xh[off + 8 * PXS]);
                ah[i][2] = __float_as_uint(Xh[off + 4]);
                ah[i][3] = __float_as_uint(Xh[off + 8 * PXS + 4]);
                al[i][0] = __float_as_uint(Xl[off]);
                al[i][1] = __float_as_uint(Xl[off + 8 * PXS]);
                al[i][2] = __float_as_uint(Xl[off + 4]);
                al[i][3] = __float_as_uint(Xl[off + 8 * PXS + 4]);
            }
#pragma unroll
            for (int j = 0; j < 4; ++j) {
                const int off = (8 * ks + t) * PWS + wn + 8 * j + g;
                bh[j][0] = __float_as_uint(Wh[off]);
                bh[j][1] = __float_as_uint(Wh[off + 4 * PWS]);
                bl[j][0] = __float_as_uint(Wl[off]);
                bl[j][1] = __float_as_uint(Wl[off + 4 * PWS]);
            }
#pragma unroll
            for (int i = 0; i < 4; ++i)
#pragma unroll
                for (int j = 0; j < 4; ++j)
                    mma3(acc[i][j], ah[i], al[i], bh[j], bl[j]);
        }
    }

#pragma unroll
    for (int j = 0; j < 4; ++j) {
        const int n = n0 + wn + 8 * j + 2 * t;
        const float b0v = bias[n], b1v = bias[n + 1];
        const int h = n >> 6, hd = n & 63;
#pragma unroll
        for (int i = 0; i < 4; ++i) {
            const int m = m0 + wm + 16 * i + g;
            const int bI = m >> 10, s = m & 1023;
            const size_t off1 = ((size_t)((bI * NH + h) * SEQ + s)) * DH + hd;
            float h0, l0, h1, l1;
            split_tf32(acc[i][j][0] + b0v, h0, l0);
            split_tf32(acc[i][j][1] + b1v, h1, l1);
            *(float2*)(outh + off1) = make_float2(h0, h1);
            *(float2*)(outl + off1) = make_float2(l0, l1);
            const int m2 = m + 8;
            const int bI2 = m2 >> 10, s2 = m2 & 1023;
            const size_t off2 = ((size_t)((bI2 * NH + h) * SEQ + s2)) * DH + hd;
            split_tf32(acc[i][j][2] + b0v, h0, l0);
            split_tf32(acc[i][j][3] + b1v, h1, l1);
            *(float2*)(outh + off2) = make_float2(h0, h1);
            *(float2*)(outl + off2) = make_float2(l0, l1);
        }
    }
}

// ---------------------------------------------------------------------------
// Attention, 3xTF32, 512 threads. cp.async double-buffered 64-row K/V stages.
//   phase 1: warp (wq,wk) computes 16q x 8k per chunk; Q-frags held in regs
//   phase 2: 2 rows/warp sparsemax|softmax; weights stored tf32-rounded
//   phase 3: out = w @ V; weight-lo dropped (w already tf32), V keeps hi/lo
// ---------------------------------------------------------------------------
constexpr int TQ  = 32;
constexpr int CK  = 64;
constexpr int NCH = SEQ / CK;     // 16
constexpr int NT  = 512;
constexpr int PSQ = 68;           // ≡4 mod 32 (phase-1 frags)
constexpr int PSV = 72;           // ≡8 mod 32 (phase-3 b-frags)
constexpr int SCP = 1028;
constexpr int KVSTG = CK * PSV;   // floats per hi (or lo) stage
constexpr int ATTN_SMEM_FLOATS = TQ * SCP + 2 * TQ * PSQ + 4 * KVSTG;
constexpr float SCALE = 0.125f;

__global__ __launch_bounds__(NT, 1) void attn_tc(const float* __restrict__ mask,
                                                 float* __restrict__ out) {
    extern __shared__ float sm[];
    float* sc  = sm;                    // [TQ][SCP]
    float* qsh = sm + TQ * SCP;         // [TQ][PSQ]
    float* qsl = qsh + TQ * PSQ;
    float* kv  = qsl + TQ * PSQ;        // 2 stages x (hi, lo)

    float* kvH[2] = { kv, kv + 2 * KVSTG };
    float* kvL[2] = { kv + KVSTG, kv + 3 * KVSTG };

    const int tid = threadIdx.x;
    const int b = blockIdx.z, h = blockIdx.y;
    const int q0 = blockIdx.x * TQ;
    const int bh_i = b * NH + h;
    const float* Qh = g_qh + ((size_t)bh_i * SEQ + q0) * DH;
    const float* Ql = g_ql + ((size_t)bh_i * SEQ + q0) * DH;
    const float* Kh = g_kh + (size_t)bh_i * SEQ * DH;
    const float* Kl = g_kl + (size_t)bh_i * SEQ * DH;
    const float* Vh = g_vh + (size_t)bh_i * SEQ * DH;
    const float* Vl = g_vl + (size_t)bh_i * SEQ * DH;
    const float* mrow = mask + b * SEQ;

    const int warp = tid >> 5, lane = tid & 31;
    const int g = lane >> 2, t = lane & 3;
    const int wq = warp >> 3;         // 0..1
    const int wk = warp & 7;          // 0..7

    // start K chunk 0, then stage q tile
    stage_cp(kvH[0], kvL[0], Kh, Kl, tid, PSQ);
    CP_COMMIT();
    {
        const int e = tid << 2;
        const int qi = e >> 6, dd = e & 63;
        *(float4*)(qsh + qi * PSQ + dd) = *(const float4*)(Qh + e);
        *(float4*)(qsl + qi * PSQ + dd) = *(const float4*)(Ql + e);
    }
    __syncthreads();

    // hoist Q fragments into registers (for all of phase 1)
    unsigned qah[8][4], qal[8][4];
#pragma unroll
    for (int ks = 0; ks < 8; ++ks) {
        const int off = (16 * wq + g) * PSQ + 8 * ks + t;
        qah[ks][0] = __float_as_uint(qsh[off]);
        qah[ks][1] = __float_as_uint(qsh[off + 8 * PSQ]);
        qah[ks][2] = __float_as_uint(qsh[off + 4]);
        qah[ks][3] = __float_as_uint(qsh[off + 8 * PSQ + 4]);
        qal[ks][0] = __float_as_uint(qsl[off]);
        qal[ks][1] = __float_as_uint(qsl[off + 8 * PSQ]);
        qal[ks][2] = __float_as_uint(qsl[off + 4]);
        qal[ks][3] = __float_as_uint(qsl[off + 8 * PSQ + 4]);
    }

    // ---- phase 1: scores ----
    for (int kc = 0; kc < NCH; ++kc) {
        if (kc + 1 < NCH) {
            stage_cp(kvH[(kc + 1) & 1], kvL[(kc + 1) & 1],
                     Kh + (size_t)(kc + 1) * CK * DH, Kl + (size_t)(kc + 1) * CK * DH,
                     tid, PSQ);
            CP_COMMIT();
            CP_WAIT(1);
        } else {
            CP_WAIT(0);
        }
        __syncthreads();

        const float* bH = kvH[kc & 1];
        const float* bL = kvL[kc & 1];
        float acc[4] = {};
#pragma unroll
        for (int ks = 0; ks < 8; ++ks) {
            unsigned bhf[2], blf[2];
            const int boff = (8 * wk + g) * PSQ + 8 * ks + t;
            bhf[0] = __float_as_uint(bH[boff]);
            bhf[1] = __float_as_uint(bH[boff + 4]);
            blf[0] = __float_as_uint(bL[boff]);
            blf[1] = __float_as_uint(bL[boff + 4]);
            mma3(acc, qah[ks], qal[ks], bhf, blf);
        }
        {
            const int s = kc * CK + 8 * wk + 2 * t;
            const float2 mv = *(const float2*)(mrow + s);
            const int q = 16 * wq + g;
            float v0 = fmaxf(fmaf(acc[0], SCALE, mv.x), -10000.0f);
            float v1 = fmaxf(fmaf(acc[1], SCALE, mv.y), -10000.0f);
            *(float2*)(sc + q * SCP + s) = make_float2(v0, v1);
            float v2 = fmaxf(fmaf(acc[2], SCALE, mv.x), -10000.0f);
            float v3 = fmaxf(fmaf(acc[3], SCALE, mv.y), -10000.0f);
            *(float2*)(sc + (q + 8) * SCP + s) = make_float2(v2, v3);
        }
        __syncthreads();
    }

    // start V chunk 0 (kv buffers are free; overlaps phase 2)
    stage_cp(kvH[0], kvL[0], Vh, Vl, tid, PSV);
    CP_COMMIT();

    // ---- phase 2: sparsemax / softmax, two independent rows per warp ----
    {
        const bool sparse = ((h & 1) == 0);
        float* row0 = sc + warp * SCP;
        float* row1 = sc + (warp + 16) * SCP;
        float z0[32], z1[32];
#pragma unroll
        for (int j = 0; j < 32; ++j) { z0[j] = row0[j * 32 + lane]; z1[j] = row1[j * 32 + lane]; }
        float mx0 = -1e30f, mx1 = -1e30f;
#pragma unroll
        for (int j = 0; j < 32; ++j) { mx0 = fmaxf(mx0, z0[j]); mx1 = fmaxf(mx1, z1[j]); }
        mx0 = warpMax(mx0);
        mx1 = warpMax(mx1);

        if (sparse) {
            float lo0 = mx0 - 1.0f, hi0 = mx0, lo1 = mx1 - 1.0f, hi1 = mx1;
            for (int it = 0; it < 26; ++it) {
                const float ta0 = 0.5f * (lo0 + hi0), ta1 = 0.5f * (lo1 + hi1);
                float s0 = 0.f, s1 = 0.f;
#pragma unroll
                for (int j = 0; j < 32; ++j) {
                    s0 += fmaxf(z0[j] - ta0, 0.f);
                    s1 += fmaxf(z1[j] - ta1, 0.f);
                }
                s0 = warpSum(s0);
                s1 = warpSum(s1);
                if (s0 > 1.0f) lo0 = ta0; else hi0 = ta0;
                if (s1 > 1.0f) lo1 = ta1; else hi1 = ta1;
            }
            const float ta0 = 0.5f * (lo0 + hi0), ta1 = 0.5f * (lo1 + hi1);
            float ss0 = 0.f, c0 = 0.f, ss1 = 0.f, c1 = 0.f;
#pragma unroll
            for (int j = 0; j < 32; ++j) {
                if (z0[j] > ta0) { ss0 += z0[j]; c0 += 1.f; }
                if (z1[j] > ta1) { ss1 += z1[j]; c1 += 1.f; }
            }
            ss0 = warpSum(ss0); c0 = warpSum(c0);
            ss1 = warpSum(ss1); c1 = warpSum(c1);
            const float tf0 = (c0 >= 0.5f) ? (ss0 - 1.0f) / c0 : ta0;
            const float tf1 = (c1 >= 0.5f) ? (ss1 - 1.0f) / c1 : ta1;
#pragma unroll
            for (int j = 0; j < 32; ++j) {
                row0[j * 32 + lane] = to_tf32(fmaxf(z0[j] - tf0, 0.f));
                row1[j * 32 + lane] = to_tf32(fmaxf(z1[j] - tf1, 0.f));
            }
        } else {
            float s0 = 0.f, s1 = 0.f;
#pragma unroll
            for (int j = 0; j < 32; ++j) {
                z0[j] = __expf(z0[j] - mx0); s0 += z0[j];
                z1[j] = __expf(z1[j] - mx1); s1 += z1[j];
            }
            s0 = warpSum(s0);
            s1 = warpSum(s1);
            const float i0 = 1.0f / s0, i1 = 1.0f / s1;
#pragma unroll
            for (int j = 0; j < 32; ++j) {
                row0[j * 32 + lane] = to_tf32(z0[j] * i0);
                row1[j * 32 + lane] = to_tf32(z1[j] * i1);
            }
        }
    }

    // ---- phase 3: out = weights @ V ----
    float oacc[4] = {};
    for (int kc = 0; kc < NCH; ++kc) {
        if (kc + 1 < NCH) {
            stage_cp(kvH[(kc + 1) & 1], kvL[(kc + 1) & 1],
                     Vh + (size_t)(kc + 1) * CK * DH, Vl + (size_t)(kc + 1) * CK * DH,
                     tid, PSV);
            CP_COMMIT();
            CP_WAIT(1);
        } else {
            CP_WAIT(0);
        }
        __syncthreads();

        const float* bH = kvH[kc & 1];
        const float* bL = kvL[kc & 1];
#pragma unroll
        for (int kk = 0; kk < CK / 8; ++kk) {
            unsigned a[4], bhf[2], blf[2];
            const float* ap = sc + (16 * wq + g) * SCP + kc * CK + 8 * kk + t;
            a[0] = __float_as_uint(ap[0]);
            a[1] = __float_as_uint(ap[8 * SCP]);
            a[2] = __float_as_uint(ap[4]);
            a[3] = __float_as_uint(ap[8 * SCP + 4]);
            const int boff = (8 * kk + t) * PSV + 8 * wk + g;
            bhf[0] = __float_as_uint(bH[boff]);
            bhf[1] = __float_as_uint(bH[boff + 4 * PSV]);
            blf[0] = __float_as_uint(bL[boff]);
            blf[1] = __float_as_uint(bL[boff + 4 * PSV]);
            mma_tf32(oacc, a, bhf);
            mma_tf32(oacc, a, blf);
        }
        __syncthreads();
    }

    // write [B, S, H*HD]
    {
        const int q = q0 + 16 * wq + g;
        float* p = out + (size_t)(b * SEQ + q) * DM + h * DH + 8 * wk + 2 * t;
        *(float2*)p = make_float2(oacc[0], oacc[1]);
        *(float2*)(p + 8 * DM) = make_float2(oacc[2], oacc[3]);
    }
}

// ---------------------------------------------------------------------------
extern "C" void kernel_launch(void* const* d_in, const int* in_sizes, int n_in,
                              void* d_out, int out_size) {
    const float* X    = (const float*)d_in[0];
    const float* Wq   = (const float*)d_in[1];
    const float* bq   = (const float*)d_in[2];
    const float* Wk   = (const float*)d_in[3];
    const float* bk   = (const float*)d_in[4];
    const float* Wv   = (const float*)d_in[5];
    const float* bv   = (const float*)d_in[6];
    const float* mask = (const float*)d_in[7];
    float* out = (float*)d_out;

    cudaFuncSetAttribute(qkv_proj_tc, cudaFuncAttributeMaxDynamicSharedMemorySize,
                         PROJ_SMEM_FLOATS * (int)sizeof(float));
    dim3 gp(DM / 128, MROWS / 128, 3);
    qkv_proj_tc<<<gp, 256, PROJ_SMEM_FLOATS * sizeof(float)>>>(X, Wq, bq, Wk, bk, Wv, bv);

    cudaFuncSetAttribute(attn_tc, cudaFuncAttributeMaxDynamicSharedMemorySize,
                         ATTN_SMEM_FLOATS * (int)sizeof(float));
    dim3 ga(SEQ / TQ, NH, NB);
    attn_tc<<<ga, NT, ATTN_SMEM_FLOATS * sizeof(float)>>>(mask, out);
}

// round 7
// speedup vs baseline: 2.5326x; 1.0415x over previous
#include <cuda_runtime.h>
#include <cstdint>

// Problem constants
#define NB   4
#define SEQ  1024
#define NH   16
#define DH   64
#define DM   1024
#define MROWS (NB * SEQ)

// Pre-split tf32 hi/lo scratch.
// Q, K: [B,H,S,DH] with in-row d-permutation pairing (d, d+4) adjacent.
// V:    [B,H,DH,S] (transposed) with the same pairing applied to s.
__device__ float g_qh[NB * NH * SEQ * DH];
__device__ float g_ql[NB * NH * SEQ * DH];
__device__ float g_kh[NB * NH * SEQ * DH];
__device__ float g_kl[NB * NH * SEQ * DH];
__device__ float g_vh[NB * NH * SEQ * DH];
__device__ float g_vl[NB * NH * SEQ * DH];

__device__ __forceinline__ int perm8(int x) { return ((x & 3) << 1) | ((x >> 2) & 1); }

__device__ __forceinline__ float to_tf32(float x) {
    unsigned u;
    asm("cvt.rna.tf32.f32 %0, %1;" : "=r"(u) : "f"(x));
    return __uint_as_float(u);
}
__device__ __forceinline__ void split_tf32(float x, float& hi, float& lo) {
    hi = to_tf32(x);
    lo = to_tf32(x - hi);
}
__device__ __forceinline__ void mma_tf32(float* c, const unsigned* a, const unsigned* b) {
    asm volatile(
        "mma.sync.aligned.m16n8k8.row.col.f32.tf32.tf32.f32 "
        "{%0,%1,%2,%3},{%4,%5,%6,%7},{%8,%9},{%0,%1,%2,%3};"
        : "+f"(c[0]), "+f"(c[1]), "+f"(c[2]), "+f"(c[3])
        : "r"(a[0]), "r"(a[1]), "r"(a[2]), "r"(a[3]), "r"(b[0]), "r"(b[1]));
}
__device__ __forceinline__ void mma3(float* c, const unsigned* ah, const unsigned* al,
                                     const unsigned* bh, const unsigned* bl) {
    mma_tf32(c, ah, bh);
    mma_tf32(c, al, bh);
    mma_tf32(c, ah, bl);
}
__device__ __forceinline__ float warpMax(float v) {
#pragma unroll
    for (int o = 16; o > 0; o >>= 1) v = fmaxf(v, __shfl_xor_sync(0xffffffffu, v, o));
    return v;
}
__device__ __forceinline__ float warpSum(float v) {
#pragma unroll
    for (int o = 16; o > 0; o >>= 1) v += __shfl_xor_sync(0xffffffffu, v, o);
    return v;
}

#define CP_COMMIT() asm volatile("cp.async.commit_group;")
#define CP_WAIT(N)  asm volatile("cp.async.wait_group %0;" :: "n"(N))

// Copy one 64-row x 64-float tile pair (hi, lo) GMEM->SMEM via cp.async.
__device__ __forceinline__ void stage_cp(float* dh, float* dl,
                                         const float* gh, const float* gl,
                                         int tid, int sstride, int gstride) {
#pragma unroll
    for (int it = 0; it < 2; ++it) {
        const int idx = tid + 512 * it;
        const int r = idx >> 4, c = (idx & 15) << 2;
        const int so = r * sstride + c;
        const size_t go = (size_t)r * gstride + c;
        uint32_t a1 = (uint32_t)__cvta_generic_to_shared(dh + so);
        uint32_t a2 = (uint32_t)__cvta_generic_to_shared(dl + so);
        asm volatile("cp.async.cg.shared.global [%0], [%1], 16;" :: "r"(a1), "l"(gh + go));
        asm volatile("cp.async.cg.shared.global [%0], [%1], 16;" :: "r"(a2), "l"(gl + go));
    }
}

// ---------------------------------------------------------------------------
// QKV projection, 3xTF32. CTA 128x128, k-stage 32, 8 warps, warp tile 64x32.
// Epilogue writes pre-split hi/lo in the MMA-friendly permuted layouts.
// ---------------------------------------------------------------------------
constexpr int PXS = 36;
constexpr int PWS = 136;
constexpr int PROJ_SMEM_FLOATS = 2 * 128 * PXS + 2 * 32 * PWS;

__global__ __launch_bounds__(256) void qkv_proj_tc(
    const float* __restrict__ X,
    const float* __restrict__ Wq, const float* __restrict__ bq,
    const float* __restrict__ Wk, const float* __restrict__ bk,
    const float* __restrict__ Wv, const float* __restrict__ bv) {
    extern __shared__ float psm[];
    float* Xh = psm;
    float* Xl = Xh + 128 * PXS;
    float* Wh = Xl + 128 * PXS;
    float* Wl = Wh + 32 * PWS;

    const float* W;
    const float* bias;
    float *outh, *outl;
    if (blockIdx.z == 0)      { W = Wq; bias = bq; outh = g_qh; outl = g_ql; }
    else if (blockIdx.z == 1) { W = Wk; bias = bk; outh = g_kh; outl = g_kl; }
    else                      { W = Wv; bias = bv; outh = g_vh; outl = g_vl; }
    const bool isV = (blockIdx.z == 2);

    const int tid = threadIdx.x;
    const int warp = tid >> 5, lane = tid & 31;
    const int g = lane >> 2, t = lane & 3;
    const int wm = (warp >> 2) * 64, wn = (warp & 3) * 32;
    const int m0 = blockIdx.y * 128, n0 = blockIdx.x * 128;

    float acc[4][4][4] = {};

    for (int k0 = 0; k0 < DM; k0 += 32) {
        __syncthreads();
#pragma unroll
        for (int it = 0; it < 4; ++it) {
            const int idx = tid + 256 * it;
            const int r = idx >> 3, c4 = (idx & 7) << 2;
            float4 v = *(const float4*)(X + (size_t)(m0 + r) * DM + k0 + c4);
            float4 hv, lv;
            split_tf32(v.x, hv.x, lv.x); split_tf32(v.y, hv.y, lv.y);
            split_tf32(v.z, hv.z, lv.z); split_tf32(v.w, hv.w, lv.w);
            *(float4*)(Xh + r * PXS + c4) = hv;
            *(float4*)(Xl + r * PXS + c4) = lv;
        }
#pragma unroll
        for (int it = 0; it < 4; ++it) {
            const int idx = tid + 256 * it;
            const int r = idx >> 5, c4 = (idx & 31) << 2;
            float4 v = *(const float4*)(W + (size_t)(k0 + r) * DM + n0 + c4);
            float4 hv, lv;
            split_tf32(v.x, hv.x, lv.x); split_tf32(v.y, hv.y, lv.y);
            split_tf32(v.z, hv.z, lv.z); split_tf32(v.w, hv.w, lv.w);
            *(float4*)(Wh + r * PWS + c4) = hv;
            *(float4*)(Wl + r * PWS + c4) = lv;
        }
        __syncthreads();

#pragma unroll
        for (int ks = 0; ks < 4; ++ks) {
            unsigned ah[4][4], al[4][4], bh[4][2], bl[4][2];
#pragma unroll
            for (int i = 0; i < 4; ++i) {
                const int off = (wm + 16 * i + g) * PXS + 8 * ks + t;
                ah[i][0] = __float_as_uint(Xh[off]);
                ah[i][1] = __float_as_uint(Xh[off + 8 * PXS]);
                ah[i][2] = __float_as_uint(Xh[off + 4]);
                ah[i][3] = __float_as_uint(Xh[off + 8 * PXS + 4]);
                al[i][0] = __float_as_uint(Xl[off]);
                al[i][1] = __float_as_uint(Xl[off + 8 * PXS]);
                al[i][2] = __float_as_uint(Xl[off + 4]);
                al[i][3] = __float_as_uint(Xl[off + 8 * PXS + 4]);
            }
#pragma unroll
            for (int j = 0; j < 4; ++j) {
                const int off = (8 * ks + t) * PWS + wn + 8 * j + g;
                bh[j][0] = __float_as_uint(Wh[off]);
                bh[j][1] = __float_as_uint(Wh[off + 4 * PWS]);
                bl[j][0] = __float_as_uint(Wl[off]);
                bl[j][1] = __float_as_uint(Wl[off + 4 * PWS]);
            }
#pragma unroll
            for (int i = 0; i < 4; ++i)
#pragma unroll
                for (int j = 0; j < 4; ++j)
                    mma3(acc[i][j], ah[i], al[i], bh[j], bl[j]);
        }
    }

    // epilogue: + bias, split, scatter into permuted layouts
#pragma unroll
    for (int j = 0; j < 4; ++j) {
        const int n = n0 + wn + 8 * j + 2 * t;
        const float b0v = bias[n], b1v = bias[n + 1];
        const int h = n >> 6, hd = n & 63;
        const int pd = (hd & ~7) | perm8(hd & 7);   // pd+2 = perm of hd+1
#pragma unroll
        for (int i = 0; i < 4; ++i) {
            const int m = m0 + wm + 16 * i + g;
            const int bI = m >> 10, s = m & 1023;
            const int m2 = m + 8;
            const int bI2 = m2 >> 10, s2 = m2 & 1023;
            float h0, l0, h1, l1, h2, l2, h3, l3;
            split_tf32(acc[i][j][0] + b0v, h0, l0);
            split_tf32(acc[i][j][1] + b1v, h1, l1);
            split_tf32(acc[i][j][2] + b0v, h2, l2);
            split_tf32(acc[i][j][3] + b1v, h3, l3);
            if (!isV) {
                const size_t b1o = ((size_t)((bI * NH + h) * SEQ + s)) * DH;
                outh[b1o + pd] = h0;  outh[b1o + pd + 2] = h1;
                outl[b1o + pd] = l0;  outl[b1o + pd + 2] = l1;
                const size_t b2o = ((size_t)((bI2 * NH + h) * SEQ + s2)) * DH;
                outh[b2o + pd] = h2;  outh[b2o + pd + 2] = h3;
                outl[b2o + pd] = l2;  outl[b2o + pd + 2] = l3;
            } else {
                const int ps1 = (s & ~7) | perm8(s & 7);
                const int ps2 = (s2 & ~7) | perm8(s2 & 7);
                const size_t r0 = ((size_t)((bI * NH + h) * DH + hd)) * SEQ;
                const size_t r1 = ((size_t)((bI * NH + h) * DH + hd + 1)) * SEQ;
                outh[r0 + ps1] = h0;  outh[r1 + ps1] = h1;
                outl[r0 + ps1] = l0;  outl[r1 + ps1] = l1;
                const size_t r0b = ((size_t)((bI2 * NH + h) * DH + hd)) * SEQ;
                const size_t r1b = ((size_t)((bI2 * NH + h) * DH + hd + 1)) * SEQ;
                outh[r0b + ps2] = h2;  outh[r1b + ps2] = h3;
                outl[r0b + ps2] = l2;  outl[r1b + ps2] = l3;
            }
        }
    }
}

// ---------------------------------------------------------------------------
// Attention, 3xTF32, 512 threads, cp.async double-buffered 64-row stages.
// All fragment loads are LDS.64 (paired layout); independent MMA chains.
// ---------------------------------------------------------------------------
constexpr int TQ  = 32;
constexpr int CK  = 64;
constexpr int NCH = SEQ / CK;     // 16
constexpr int NT  = 512;
constexpr int PS  = 72;           // ≡8 mod 32: LDS.64 frag loads conflict-free
constexpr int SCP = 1032;         // ≡8 mod 32
constexpr int KVSTG = CK * PS;
constexpr int ATTN_SMEM_FLOATS = TQ * SCP + 2 * TQ * PS + 4 * KVSTG;
constexpr float SCALE = 0.125f;

__global__ __launch_bounds__(NT, 1) void attn_tc(const float* __restrict__ mask,
                                                 float* __restrict__ out) {
    extern __shared__ float sm[];
    float* sc  = sm;                    // [TQ][SCP] scores (columns perm8'd per 8-group)
    float* qsh = sm + TQ * SCP;         // [TQ][PS]
    float* qsl = qsh + TQ * PS;
    float* kv  = qsl + TQ * PS;         // 2 stages x (hi, lo)

    float* kvH[2] = { kv, kv + 2 * KVSTG };
    float* kvL[2] = { kv + KVSTG, kv + 3 * KVSTG };

    const int tid = threadIdx.x;
    const int b = blockIdx.z, h = blockIdx.y;
    const int q0 = blockIdx.x * TQ;
    const int bh_i = b * NH + h;
    const float* Qh = g_qh + ((size_t)bh_i * SEQ + q0) * DH;
    const float* Ql = g_ql + ((size_t)bh_i * SEQ + q0) * DH;
    const float* Kh = g_kh + (size_t)bh_i * SEQ * DH;
    const float* Kl = g_kl + (size_t)bh_i * SEQ * DH;
    const float* Vh = g_vh + (size_t)bh_i * DH * SEQ;   // [d][s] layout
    const float* Vl = g_vl + (size_t)bh_i * DH * SEQ;
    const float* mrow = mask + b * SEQ;

    const int warp = tid >> 5, lane = tid & 31;
    const int g = lane >> 2, t = lane & 3;
    const int wq = warp >> 3;         // 0..1
    const int wk = warp & 7;          // 0..7

    // start K chunk 0; stage q tile
    stage_cp(kvH[0], kvL[0], Kh, Kl, tid, PS, DH);
    CP_COMMIT();
    {
        const int e = tid << 2;
        const int qi = e >> 6, dd = e & 63;
        *(float4*)(qsh + qi * PS + dd) = *(const float4*)(Qh + e);
        *(float4*)(qsl + qi * PS + dd) = *(const float4*)(Ql + e);
    }
    __syncthreads();

    // hoist Q fragments (LDS.64 pairs)
    unsigned qah[8][4], qal[8][4];
#pragma unroll
    for (int ks = 0; ks < 8; ++ks) {
        const int off = (16 * wq + g) * PS + 8 * ks + 2 * t;
        float2 f0 = *(const float2*)(qsh + off);
        float2 f1 = *(const float2*)(qsh + off + 8 * PS);
        qah[ks][0] = __float_as_uint(f0.x);
        qah[ks][1] = __float_as_uint(f1.x);
        qah[ks][2] = __float_as_uint(f0.y);
        qah[ks][3] = __float_as_uint(f1.y);
        float2 e0 = *(const float2*)(qsl + off);
        float2 e1 = *(const float2*)(qsl + off + 8 * PS);
        qal[ks][0] = __float_as_uint(e0.x);
        qal[ks][1] = __float_as_uint(e1.x);
        qal[ks][2] = __float_as_uint(e0.y);
        qal[ks][3] = __float_as_uint(e1.y);
    }

    const int p0 = perm8(2 * t);   // score store position for actual col 2t (p0+2 for 2t+1)

    // ---- phase 1: scores ----
    for (int kc = 0; kc < NCH; ++kc) {
        if (kc + 1 < NCH) {
            stage_cp(kvH[(kc + 1) & 1], kvL[(kc + 1) & 1],
                     Kh + (size_t)(kc + 1) * CK * DH, Kl + (size_t)(kc + 1) * CK * DH,
                     tid, PS, DH);
            CP_COMMIT();
            CP_WAIT(1);
        } else {
            CP_WAIT(0);
        }
        __syncthreads();

        const float* bH = kvH[kc & 1];
        const float* bL = kvL[kc & 1];
        float a1[4] = {}, a2[4] = {}, a3[4] = {};   // 3 independent chains
#pragma unroll
        for (int ks = 0; ks < 8; ++ks) {
            const int boff = (8 * wk + g) * PS + 8 * ks + 2 * t;
            float2 fb = *(const float2*)(bH + boff);
            float2 fl = *(const float2*)(bL + boff);
            unsigned bhf[2] = { __float_as_uint(fb.x), __float_as_uint(fb.y) };
            unsigned blf[2] = { __float_as_uint(fl.x), __float_as_uint(fl.y) };
            mma_tf32(a1, qah[ks], bhf);
            mma_tf32(a2, qal[ks], bhf);
            mma_tf32(a3, qah[ks], blf);
        }
        {
            const int bs = kc * CK + 8 * wk;
            const float2 mv = *(const float2*)(mrow + bs + 2 * t);
            const int q = 16 * wq + g;
            float c0 = a1[0] + a2[0] + a3[0];
            float c1 = a1[1] + a2[1] + a3[1];
            float c2 = a1[2] + a2[2] + a3[2];
            float c3 = a1[3] + a2[3] + a3[3];
            sc[q * SCP + bs + p0]           = fmaxf(fmaf(c0, SCALE, mv.x), -10000.0f);
            sc[q * SCP + bs + p0 + 2]       = fmaxf(fmaf(c1, SCALE, mv.y), -10000.0f);
            sc[(q + 8) * SCP + bs + p0]     = fmaxf(fmaf(c2, SCALE, mv.x), -10000.0f);
            sc[(q + 8) * SCP + bs + p0 + 2] = fmaxf(fmaf(c3, SCALE, mv.y), -10000.0f);
        }
        __syncthreads();
    }

    // start V chunk 0 (kv buffers free; overlaps phase 2)
    stage_cp(kvH[0], kvL[0], Vh, Vl, tid, PS, SEQ);
    CP_COMMIT();

    // ---- phase 2: sparsemax / softmax, two independent rows per warp ----
    {
        const bool sparse = ((h & 1) == 0);
        float* row0 = sc + warp * SCP;
        float* row1 = sc + (warp + 16) * SCP;
        float z0[32], z1[32];
#pragma unroll
        for (int j = 0; j < 32; ++j) { z0[j] = row0[j * 32 + lane]; z1[j] = row1[j * 32 + lane]; }
        float mx0 = -1e30f, mx1 = -1e30f;
#pragma unroll
        for (int j = 0; j < 32; ++j) { mx0 = fmaxf(mx0, z0[j]); mx1 = fmaxf(mx1, z1[j]); }
        mx0 = warpMax(mx0);
        mx1 = warpMax(mx1);

        if (sparse) {
            float lo0 = mx0 - 1.0f, hi0 = mx0, lo1 = mx1 - 1.0f, hi1 = mx1;
            for (int it = 0; it < 26; ++it) {
                const float ta0 = 0.5f * (lo0 + hi0), ta1 = 0.5f * (lo1 + hi1);
                float s0 = 0.f, s1 = 0.f;
#pragma unroll
                for (int j = 0; j < 32; ++j) {
                    s0 += fmaxf(z0[j] - ta0, 0.f);
                    s1 += fmaxf(z1[j] - ta1, 0.f);
                }
                s0 = warpSum(s0);
                s1 = warpSum(s1);
                if (s0 > 1.0f) lo0 = ta0; else hi0 = ta0;
                if (s1 > 1.0f) lo1 = ta1; else hi1 = ta1;
            }
            const float ta0 = 0.5f * (lo0 + hi0), ta1 = 0.5f * (lo1 + hi1);
            float ss0 = 0.f, c0 = 0.f, ss1 = 0.f, c1 = 0.f;
#pragma unroll
            for (int j = 0; j < 32; ++j) {
                if (z0[j] > ta0) { ss0 += z0[j]; c0 += 1.f; }
                if (z1[j] > ta1) { ss1 += z1[j]; c1 += 1.f; }
            }
            ss0 = warpSum(ss0); c0 = warpSum(c0);
            ss1 = warpSum(ss1); c1 = warpSum(c1);
            const float tf0 = (c0 >= 0.5f) ? (ss0 - 1.0f) / c0 : ta0;
            const float tf1 = (c1 >= 0.5f) ? (ss1 - 1.0f) / c1 : ta1;
#pragma unroll
            for (int j = 0; j < 32; ++j) {
                row0[j * 32 + lane] = to_tf32(fmaxf(z0[j] - tf0, 0.f));
                row1[j * 32 + lane] = to_tf32(fmaxf(z1[j] - tf1, 0.f));
            }
        } else {
            float s0 = 0.f, s1 = 0.f;
#pragma unroll
            for (int j = 0; j < 32; ++j) {
                z0[j] = __expf(z0[j] - mx0); s0 += z0[j];
                z1[j] = __expf(z1[j] - mx1); s1 += z1[j];
            }
            s0 = warpSum(s0);
            s1 = warpSum(s1);
            const float i0 = 1.0f / s0, i1 = 1.0f / s1;
#pragma unroll
            for (int j = 0; j < 32; ++j) {
                row0[j * 32 + lane] = to_tf32(z0[j] * i0);
                row1[j * 32 + lane] = to_tf32(z1[j] * i1);
            }
        }
    }

    // ---- phase 3: out = weights @ V ----
    float o1[4] = {}, o2[4] = {};      // 2 independent chains
    for (int kc = 0; kc < NCH; ++kc) {
        if (kc + 1 < NCH) {
            stage_cp(kvH[(kc + 1) & 1], kvL[(kc + 1) & 1],
                     Vh + (kc + 1) * CK, Vl + (kc + 1) * CK,
                     tid, PS, SEQ);
            CP_COMMIT();
            CP_WAIT(1);
        } else {
            CP_WAIT(0);
        }
        __syncthreads();

        const float* bH = kvH[kc & 1];
        const float* bL = kvL[kc & 1];
#pragma unroll
        for (int kk = 0; kk < CK / 8; ++kk) {
            const float* ap = sc + (16 * wq + g) * SCP + kc * CK + 8 * kk + 2 * t;
            float2 fa0 = *(const float2*)(ap);
            float2 fa1 = *(const float2*)(ap + 8 * SCP);
            unsigned a[4] = { __float_as_uint(fa0.x), __float_as_uint(fa1.x),
                              __float_as_uint(fa0.y), __float_as_uint(fa1.y) };
            const int boff = (8 * wk + g) * PS + 8 * kk + 2 * t;
            float2 fbh = *(const float2*)(bH + boff);
            float2 fbl = *(const float2*)(bL + boff);
            unsigned bhf[2] = { __float_as_uint(fbh.x), __float_as_uint(fbh.y) };
            unsigned blf[2] = { __float_as_uint(fbl.x), __float_as_uint(fbl.y) };
            mma_tf32(o1, a, bhf);
            mma_tf32(o2, a, blf);
        }
        __syncthreads();
    }

    // write [B, S, H*HD]
    {
        const int q = q0 + 16 * wq + g;
        float* p = out + (size_t)(b * SEQ + q) * DM + h * DH + 8 * wk + 2 * t;
        *(float2*)p = make_float2(o1[0] + o2[0], o1[1] + o2[1]);
        *(float2*)(p + 8 * DM) = make_float2(o1[2] + o2[2], o1[3] + o2[3]);
    }
}

// ---------------------------------------------------------------------------
extern "C" void kernel_launch(void* const* d_in, const int* in_sizes, int n_in,
                              void* d_out, int out_size) {
    const float* X    = (const float*)d_in[0];
    const float* Wq   = (const float*)d_in[1];
    const float* bq   = (const float*)d_in[2];
    const float* Wk   = (const float*)d_in[3];
    const float* bk   = (const float*)d_in[4];
    const float* Wv   = (const float*)d_in[5];
    const float* bv   = (const float*)d_in[6];
    const float* mask = (const float*)d_in[7];
    float* out = (float*)d_out;

    cudaFuncSetAttribute(qkv_proj_tc, cudaFuncAttributeMaxDynamicSharedMemorySize,
                         PROJ_SMEM_FLOATS * (int)sizeof(float));
    dim3 gp(DM / 128, MROWS / 128, 3);
    qkv_proj_tc<<<gp, 256, PROJ_SMEM_FLOATS * sizeof(float)>>>(X, Wq, bq, Wk, bk, Wv, bv);

    cudaFuncSetAttribute(attn_tc, cudaFuncAttributeMaxDynamicSharedMemorySize,
                         ATTN_SMEM_FLOATS * (int)sizeof(float));
    dim3 ga(SEQ / TQ, NH, NB);
    attn_tc<<<ga, NT, ATTN_SMEM_FLOATS * sizeof(float)>>>(mask, out);
}

// round 8
// speedup vs baseline: 2.8293x; 1.1172x over previous
#include <cuda_runtime.h>
#include <cstdint>

// Problem constants
#define NB   4
#define SEQ  1024
#define NH   16
#define DH   64
#define DM   1024
#define MROWS (NB * SEQ)

// Pre-split tf32 hi/lo scratch.
// Q, K: [B,H,S,DH] with in-row d-permutation pairing (d, d+4) adjacent.
// V:    [B,H,DH,S] (transposed) with the same pairing applied to s.
__device__ float g_qh[NB * NH * SEQ * DH];
__device__ float g_ql[NB * NH * SEQ * DH];
__device__ float g_kh[NB * NH * SEQ * DH];
__device__ float g_kl[NB * NH * SEQ * DH];
__device__ float g_vh[NB * NH * SEQ * DH];
__device__ float g_vl[NB * NH * SEQ * DH];

__device__ __forceinline__ int perm8(int x) { return ((x & 3) << 1) | ((x >> 2) & 1); }

__device__ __forceinline__ float to_tf32(float x) {
    unsigned u;
    asm("cvt.rna.tf32.f32 %0, %1;" : "=r"(u) : "f"(x));
    return __uint_as_float(u);
}
__device__ __forceinline__ void split_tf32(float x, float& hi, float& lo) {
    hi = to_tf32(x);
    lo = to_tf32(x - hi);
}
__device__ __forceinline__ void mma_tf32(float* c, const unsigned* a, const unsigned* b) {
    asm volatile(
        "mma.sync.aligned.m16n8k8.row.col.f32.tf32.tf32.f32 "
        "{%0,%1,%2,%3},{%4,%5,%6,%7},{%8,%9},{%0,%1,%2,%3};"
        : "+f"(c[0]), "+f"(c[1]), "+f"(c[2]), "+f"(c[3])
        : "r"(a[0]), "r"(a[1]), "r"(a[2]), "r"(a[3]), "r"(b[0]), "r"(b[1]));
}
__device__ __forceinline__ float warpMax(float v) {
#pragma unroll
    for (int o = 16; o > 0; o >>= 1) v = fmaxf(v, __shfl_xor_sync(0xffffffffu, v, o));
    return v;
}
__device__ __forceinline__ float warpSum(float v) {
#pragma unroll
    for (int o = 16; o > 0; o >>= 1) v += __shfl_xor_sync(0xffffffffu, v, o);
    return v;
}

#define CP_COMMIT() asm volatile("cp.async.commit_group;")
#define CP_WAIT(N)  asm volatile("cp.async.wait_group %0;" :: "n"(N))

// Copy one 64-row x 64-float tile pair (hi, lo) GMEM->SMEM via cp.async.
__device__ __forceinline__ void stage_cp(float* dh, float* dl,
                                         const float* gh, const float* gl,
                                         int tid, int sstride, int gstride) {
#pragma unroll
    for (int it = 0; it < 2; ++it) {
        const int idx = tid + 512 * it;
        const int r = idx >> 4, c = (idx & 15) << 2;
        const int so = r * sstride + c;
        const size_t go = (size_t)r * gstride + c;
        uint32_t a1 = (uint32_t)__cvta_generic_to_shared(dh + so);
        uint32_t a2 = (uint32_t)__cvta_generic_to_shared(dl + so);
        asm volatile("cp.async.cg.shared.global [%0], [%1], 16;" :: "r"(a1), "l"(gh + go));
        asm volatile("cp.async.cg.shared.global [%0], [%1], 16;" :: "r"(a2), "l"(gl + go));
    }
}

// ---------------------------------------------------------------------------
// QKV projection, 3xTF32, independent-chain MMA scheduling.
// CTA 128x128, k-stage 32, 8 warps, warp tile 64x32.
// ---------------------------------------------------------------------------
constexpr int PXS = 36;
constexpr int PWS = 136;
constexpr int PROJ_SMEM_FLOATS = 2 * 128 * PXS + 2 * 32 * PWS;

__global__ __launch_bounds__(256) void qkv_proj_tc(
    const float* __restrict__ X,
    const float* __restrict__ Wq, const float* __restrict__ bq,
    const float* __restrict__ Wk, const float* __restrict__ bk,
    const float* __restrict__ Wv, const float* __restrict__ bv) {
    extern __shared__ float psm[];
    float* Xh = psm;
    float* Xl = Xh + 128 * PXS;
    float* Wh = Xl + 128 * PXS;
    float* Wl = Wh + 32 * PWS;

    const float* W;
    const float* bias;
    float *outh, *outl;
    if (blockIdx.z == 0)      { W = Wq; bias = bq; outh = g_qh; outl = g_ql; }
    else if (blockIdx.z == 1) { W = Wk; bias = bk; outh = g_kh; outl = g_kl; }
    else                      { W = Wv; bias = bv; outh = g_vh; outl = g_vl; }
    const bool isV = (blockIdx.z == 2);

    const int tid = threadIdx.x;
    const int warp = tid >> 5, lane = tid & 31;
    const int g = lane >> 2, t = lane & 3;
    const int wm = (warp >> 2) * 64, wn = (warp & 3) * 32;
    const int m0 = blockIdx.y * 128, n0 = blockIdx.x * 128;

    float acc[4][4][4] = {};

    for (int k0 = 0; k0 < DM; k0 += 32) {
        __syncthreads();
#pragma unroll
        for (int it = 0; it < 4; ++it) {
            const int idx = tid + 256 * it;
            const int r = idx >> 3, c4 = (idx & 7) << 2;
            float4 v = *(const float4*)(X + (size_t)(m0 + r) * DM + k0 + c4);
            float4 hv, lv;
            split_tf32(v.x, hv.x, lv.x); split_tf32(v.y, hv.y, lv.y);
            split_tf32(v.z, hv.z, lv.z); split_tf32(v.w, hv.w, lv.w);
            *(float4*)(Xh + r * PXS + c4) = hv;
            *(float4*)(Xl + r * PXS + c4) = lv;
        }
#pragma unroll
        for (int it = 0; it < 4; ++it) {
            const int idx = tid + 256 * it;
            const int r = idx >> 5, c4 = (idx & 31) << 2;
            float4 v = *(const float4*)(W + (size_t)(k0 + r) * DM + n0 + c4);
            float4 hv, lv;
            split_tf32(v.x, hv.x, lv.x); split_tf32(v.y, hv.y, lv.y);
            split_tf32(v.z, hv.z, lv.z); split_tf32(v.w, hv.w, lv.w);
            *(float4*)(Wh + r * PWS + c4) = hv;
            *(float4*)(Wl + r * PWS + c4) = lv;
        }
        __syncthreads();

#pragma unroll
        for (int ks = 0; ks < 4; ++ks) {
            unsigned ah[4][4], al[4][4], bh[4][2], bl[4][2];
#pragma unroll
            for (int i = 0; i < 4; ++i) {
                const int off = (wm + 16 * i + g) * PXS + 8 * ks + t;
                ah[i][0] = __float_as_uint(Xh[off]);
                ah[i][1] = __float_as_uint(Xh[off + 8 * PXS]);
                ah[i][2] = __float_as_uint(Xh[off + 4]);
                ah[i][3] = __float_as_uint(Xh[off + 8 * PXS + 4]);
                al[i][0] = __float_as_uint(Xl[off]);
                al[i][1] = __float_as_uint(Xl[off + 8 * PXS]);
                al[i][2] = __float_as_uint(Xl[off + 4]);
                al[i][3] = __float_as_uint(Xl[off + 8 * PXS + 4]);
            }
#pragma unroll
            for (int j = 0; j < 4; ++j) {
                const int off = (8 * ks + t) * PWS + wn + 8 * j + g;
                bh[j][0] = __float_as_uint(Wh[off]);
                bh[j][1] = __float_as_uint(Wh[off + 4 * PWS]);
                bl[j][0] = __float_as_uint(Wl[off]);
                bl[j][1] = __float_as_uint(Wl[off + 4 * PWS]);
            }
            // three sweeps of 16 INDEPENDENT MMAs each (no back-to-back RAW)
#pragma unroll
            for (int i = 0; i < 4; ++i)
#pragma unroll
                for (int j = 0; j < 4; ++j)
                    mma_tf32(acc[i][j], ah[i], bh[j]);
#pragma unroll
            for (int i = 0; i < 4; ++i)
#pragma unroll
                for (int j = 0; j < 4; ++j)
                    mma_tf32(acc[i][j], al[i], bh[j]);
#pragma unroll
            for (int i = 0; i < 4; ++i)
#pragma unroll
                for (int j = 0; j < 4; ++j)
                    mma_tf32(acc[i][j], ah[i], bl[j]);
        }
    }

    // epilogue: + bias, split, scatter into permuted layouts
#pragma unroll
    for (int j = 0; j < 4; ++j) {
        const int n = n0 + wn + 8 * j + 2 * t;
        const float b0v = bias[n], b1v = bias[n + 1];
        const int h = n >> 6, hd = n & 63;
        const int pd = (hd & ~7) | perm8(hd & 7);
#pragma unroll
        for (int i = 0; i < 4; ++i) {
            const int m = m0 + wm + 16 * i + g;
            const int bI = m >> 10, s = m & 1023;
            const int m2 = m + 8;
            const int bI2 = m2 >> 10, s2 = m2 & 1023;
            float h0, l0, h1, l1, h2, l2, h3, l3;
            split_tf32(acc[i][j][0] + b0v, h0, l0);
            split_tf32(acc[i][j][1] + b1v, h1, l1);
            split_tf32(acc[i][j][2] + b0v, h2, l2);
            split_tf32(acc[i][j][3] + b1v, h3, l3);
            if (!isV) {
                const size_t b1o = ((size_t)((bI * NH + h) * SEQ + s)) * DH;
                outh[b1o + pd] = h0;  outh[b1o + pd + 2] = h1;
                outl[b1o + pd] = l0;  outl[b1o + pd + 2] = l1;
                const size_t b2o = ((size_t)((bI2 * NH + h) * SEQ + s2)) * DH;
                outh[b2o + pd] = h2;  outh[b2o + pd + 2] = h3;
                outl[b2o + pd] = l2;  outl[b2o + pd + 2] = l3;
            } else {
                const int ps1 = (s & ~7) | perm8(s & 7);
                const int ps2 = (s2 & ~7) | perm8(s2 & 7);
                const size_t r0 = ((size_t)((bI * NH + h) * DH + hd)) * SEQ;
                const size_t r1 = ((size_t)((bI * NH + h) * DH + hd + 1)) * SEQ;
                outh[r0 + ps1] = h0;  outh[r1 + ps1] = h1;
                outl[r0 + ps1] = l0;  outl[r1 + ps1] = l1;
                const size_t r0b = ((size_t)((bI2 * NH + h) * DH + hd)) * SEQ;
                const size_t r1b = ((size_t)((bI2 * NH + h) * DH + hd + 1)) * SEQ;
                outh[r0b + ps2] = h2;  outh[r1b + ps2] = h3;
                outl[r0b + ps2] = l2;  outl[r1b + ps2] = l3;
            }
        }
    }
}

// ---------------------------------------------------------------------------
// Attention, 3xTF32, 512 threads, cp.async double-buffer, 1 barrier/chunk.
// Phase 2: Michelot fixed-point sparsemax (exact, ~5 iterations).
// ---------------------------------------------------------------------------
constexpr int TQ  = 32;
constexpr int CK  = 64;
constexpr int NCH = SEQ / CK;     // 16
constexpr int NT  = 512;
constexpr int PS  = 72;
constexpr int SCP = 1032;
constexpr int KVSTG = CK * PS;
constexpr int ATTN_SMEM_FLOATS = TQ * SCP + 2 * TQ * PS + 4 * KVSTG;
constexpr float SCALE = 0.125f;

__global__ __launch_bounds__(NT, 1) void attn_tc(const float* __restrict__ mask,
                                                 float* __restrict__ out) {
    extern __shared__ float sm[];
    float* sc  = sm;                    // [TQ][SCP]
    float* qsh = sm + TQ * SCP;         // [TQ][PS]
    float* qsl = qsh + TQ * PS;
    float* kv  = qsl + TQ * PS;

    float* kvH[2] = { kv, kv + 2 * KVSTG };
    float* kvL[2] = { kv + KVSTG, kv + 3 * KVSTG };

    const int tid = threadIdx.x;
    const int b = blockIdx.z, h = blockIdx.y;
    const int q0 = blockIdx.x * TQ;
    const int bh_i = b * NH + h;
    const float* Qh = g_qh + ((size_t)bh_i * SEQ + q0) * DH;
    const float* Ql = g_ql + ((size_t)bh_i * SEQ + q0) * DH;
    const float* Kh = g_kh + (size_t)bh_i * SEQ * DH;
    const float* Kl = g_kl + (size_t)bh_i * SEQ * DH;
    const float* Vh = g_vh + (size_t)bh_i * DH * SEQ;
    const float* Vl = g_vl + (size_t)bh_i * DH * SEQ;
    const float* mrow = mask + b * SEQ;

    const int warp = tid >> 5, lane = tid & 31;
    const int g = lane >> 2, t = lane & 3;
    const int wq = warp >> 3;
    const int wk = warp & 7;

    // stage K chunk 0; stage q tile
    stage_cp(kvH[0], kvL[0], Kh, Kl, tid, PS, DH);
    CP_COMMIT();
    {
        const int e = tid << 2;
        const int qi = e >> 6, dd = e & 63;
        *(float4*)(qsh + qi * PS + dd) = *(const float4*)(Qh + e);
        *(float4*)(qsl + qi * PS + dd) = *(const float4*)(Ql + e);
    }
    __syncthreads();

    // hoist Q fragments (LDS.64 pairs)
    unsigned qah[8][4], qal[8][4];
#pragma unroll
    for (int ks = 0; ks < 8; ++ks) {
        const int off = (16 * wq + g) * PS + 8 * ks + 2 * t;
        float2 f0 = *(const float2*)(qsh + off);
        float2 f1 = *(const float2*)(qsh + off + 8 * PS);
        qah[ks][0] = __float_as_uint(f0.x);
        qah[ks][1] = __float_as_uint(f1.x);
        qah[ks][2] = __float_as_uint(f0.y);
        qah[ks][3] = __float_as_uint(f1.y);
        float2 e0 = *(const float2*)(qsl + off);
        float2 e1 = *(const float2*)(qsl + off + 8 * PS);
        qal[ks][0] = __float_as_uint(e0.x);
        qal[ks][1] = __float_as_uint(e1.x);
        qal[ks][2] = __float_as_uint(e0.y);
        qal[ks][3] = __float_as_uint(e1.y);
    }

    const int p0 = perm8(2 * t);

    // ---- phase 1: scores, single barrier per chunk ----
    for (int kc = 0; kc < NCH; ++kc) {
        CP_WAIT(0);
        __syncthreads();          // stage kc visible; prev buffer free
        if (kc + 1 < NCH) {
            stage_cp(kvH[(kc + 1) & 1], kvL[(kc + 1) & 1],
                     Kh + (size_t)(kc + 1) * CK * DH, Kl + (size_t)(kc + 1) * CK * DH,
                     tid, PS, DH);
            CP_COMMIT();
        }

        const float* bH = kvH[kc & 1];
        const float* bL = kvL[kc & 1];
        float a1[4] = {}, a2[4] = {}, a3[4] = {};
#pragma unroll
        for (int ks = 0; ks < 8; ++ks) {
            const int boff = (8 * wk + g) * PS + 8 * ks + 2 * t;
            float2 fb = *(const float2*)(bH + boff);
            float2 fl = *(const float2*)(bL + boff);
            unsigned bhf[2] = { __float_as_uint(fb.x), __float_as_uint(fb.y) };
            unsigned blf[2] = { __float_as_uint(fl.x), __float_as_uint(fl.y) };
            mma_tf32(a1, qah[ks], bhf);
            mma_tf32(a2, qal[ks], bhf);
            mma_tf32(a3, qah[ks], blf);
        }
        {
            const int bs = kc * CK + 8 * wk;
            const float2 mv = *(const float2*)(mrow + bs + 2 * t);
            const int q = 16 * wq + g;
            float c0 = a1[0] + a2[0] + a3[0];
            float c1 = a1[1] + a2[1] + a3[1];
            float c2 = a1[2] + a2[2] + a3[2];
            float c3 = a1[3] + a2[3] + a3[3];
            sc[q * SCP + bs + p0]           = fmaxf(fmaf(c0, SCALE, mv.x), -10000.0f);
            sc[q * SCP + bs + p0 + 2]       = fmaxf(fmaf(c1, SCALE, mv.y), -10000.0f);
            sc[(q + 8) * SCP + bs + p0]     = fmaxf(fmaf(c2, SCALE, mv.x), -10000.0f);
            sc[(q + 8) * SCP + bs + p0 + 2] = fmaxf(fmaf(c3, SCALE, mv.y), -10000.0f);
        }
    }

    // stage V chunk 0 (buf[0] free: protected by barrier at top of kc=15)
    stage_cp(kvH[0], kvL[0], Vh, Vl, tid, PS, SEQ);
    CP_COMMIT();
    __syncthreads();   // all sc writes visible for phase 2

    // ---- phase 2: Michelot sparsemax / softmax, 2 rows per warp ----
    {
        const bool sparse = ((h & 1) == 0);
        float* row0 = sc + warp * SCP;
        float* row1 = sc + (warp + 16) * SCP;
        float z0[32], z1[32];
#pragma unroll
        for (int j = 0; j < 32; ++j) { z0[j] = row0[j * 32 + lane]; z1[j] = row1[j * 32 + lane]; }
        float mx0 = -1e30f, mx1 = -1e30f;
#pragma unroll
        for (int j = 0; j < 32; ++j) { mx0 = fmaxf(mx0, z0[j]); mx1 = fmaxf(mx1, z1[j]); }
        mx0 = warpMax(mx0);
        mx1 = warpMax(mx1);

        if (sparse) {
            // Michelot: tau <- (sum_{z>tau} z - 1)/|{z>tau}|, from tau = mx-1.
            // Monotone nondecreasing; fixed point is the exact sparsemax tau.
            float tau0 = mx0 - 1.0f, tau1 = mx1 - 1.0f;
            for (int it = 0; it < 24; ++it) {
                float sa0 = 0.f, sb0 = 0.f, sc0 = 0.f, sd0 = 0.f;
                float ca0 = 0.f, cb0 = 0.f, cc0 = 0.f, cd0 = 0.f;
                float sa1 = 0.f, sb1 = 0.f, sc1 = 0.f, sd1 = 0.f;
                float ca1 = 0.f, cb1 = 0.f, cc1 = 0.f, cd1 = 0.f;
#pragma unroll
                for (int j = 0; j < 32; j += 4) {
                    if (z0[j]     > tau0) { sa0 += z0[j];     ca0 += 1.f; }
                    if (z0[j + 1] > tau0) { sb0 += z0[j + 1]; cb0 += 1.f; }
                    if (z0[j + 2] > tau0) { sc0 += z0[j + 2]; cc0 += 1.f; }
                    if (z0[j + 3] > tau0) { sd0 += z0[j + 3]; cd0 += 1.f; }
                    if (z1[j]     > tau1) { sa1 += z1[j];     ca1 += 1.f; }
                    if (z1[j + 1] > tau1) { sb1 += z1[j + 1]; cb1 += 1.f; }
                    if (z1[j + 2] > tau1) { sc1 += z1[j + 2]; cc1 += 1.f; }
                    if (z1[j + 3] > tau1) { sd1 += z1[j + 3]; cd1 += 1.f; }
                }
                float s0 = (sa0 + sb0) + (sc0 + sd0);
                float c0 = (ca0 + cb0) + (cc0 + cd0);
                float s1 = (sa1 + sb1) + (sc1 + sd1);
                float c1 = (ca1 + cb1) + (cc1 + cd1);
                s0 = warpSum(s0);
                c0 = warpSum(c0);
                s1 = warpSum(s1);
                c1 = warpSum(c1);
                const float nt0 = (s0 - 1.0f) / c0;   // c >= 1 (z=mx > tau always)
                const float nt1 = (s1 - 1.0f) / c1;
                const bool done = (nt0 == tau0) && (nt1 == tau1);  // uniform
                tau0 = nt0;
                tau1 = nt1;
                if (done) break;
            }
#pragma unroll
            for (int j = 0; j < 32; ++j) {
                row0[j * 32 + lane] = to_tf32(fmaxf(z0[j] - tau0, 0.f));
                row1[j * 32 + lane] = to_tf32(fmaxf(z1[j] - tau1, 0.f));
            }
        } else {
            float s0 = 0.f, s1 = 0.f;
#pragma unroll
            for (int j = 0; j < 32; ++j) {
                z0[j] = __expf(z0[j] - mx0); s0 += z0[j];
                z1[j] = __expf(z1[j] - mx1); s1 += z1[j];
            }
            s0 = warpSum(s0);
            s1 = warpSum(s1);
            const float i0 = 1.0f / s0, i1 = 1.0f / s1;
#pragma unroll
            for (int j = 0; j < 32; ++j) {
                row0[j * 32 + lane] = to_tf32(z0[j] * i0);
                row1[j * 32 + lane] = to_tf32(z1[j] * i1);
            }
        }
    }

    // ---- phase 3: out = weights @ V, single barrier per chunk ----
    float o1[4] = {}, o2[4] = {};
    for (int kc = 0; kc < NCH; ++kc) {
        CP_WAIT(0);
        __syncthreads();          // stage kc visible; prev buffer free; (kc=0: sc ready)
        if (kc + 1 < NCH) {
            stage_cp(kvH[(kc + 1) & 1], kvL[(kc + 1) & 1],
                     Vh + (kc + 1) * CK, Vl + (kc + 1) * CK,
                     tid, PS, SEQ);
            CP_COMMIT();
        }

        const float* bH = kvH[kc & 1];
        const float* bL = kvL[kc & 1];
#pragma unroll
        for (int kk = 0; kk < CK / 8; ++kk) {
            const float* ap = sc + (16 * wq + g) * SCP + kc * CK + 8 * kk + 2 * t;
            float2 fa0 = *(const float2*)(ap);
            float2 fa1 = *(const float2*)(ap + 8 * SCP);
            unsigned a[4] = { __float_as_uint(fa0.x), __float_as_uint(fa1.x),
                              __float_as_uint(fa0.y), __float_as_uint(fa1.y) };
            const int boff = (8 * wk + g) * PS + 8 * kk + 2 * t;
            float2 fbh = *(const float2*)(bH + boff);
            float2 fbl = *(const float2*)(bL + boff);
            unsigned bhf[2] = { __float_as_uint(fbh.x), __float_as_uint(fbh.y) };
            unsigned blf[2] = { __float_as_uint(fbl.x), __float_as_uint(fbl.y) };
            mma_tf32(o1, a, bhf);
            mma_tf32(o2, a, blf);
        }
    }

    // write [B, S, H*HD]
    {
        const int q = q0 + 16 * wq + g;
        float* p = out + (size_t)(b * SEQ + q) * DM + h * DH + 8 * wk + 2 * t;
        *(float2*)p = make_float2(o1[0] + o2[0], o1[1] + o2[1]);
        *(float2*)(p + 8 * DM) = make_float2(o1[2] + o2[2], o1[3] + o2[3]);
    }
}

// ---------------------------------------------------------------------------
extern "C" void kernel_launch(void* const* d_in, const int* in_sizes, int n_in,
                              void* d_out, int out_size) {
    const float* X    = (const float*)d_in[0];
    const float* Wq   = (const float*)d_in[1];
    const float* bq   = (const float*)d_in[2];
    const float* Wk   = (const float*)d_in[3];
    const float* bk   = (const float*)d_in[4];
    const float* Wv   = (const float*)d_in[5];
    const float* bv   = (const float*)d_in[6];
    const float* mask = (const float*)d_in[7];
    float* out = (float*)d_out;

    cudaFuncSetAttribute(qkv_proj_tc, cudaFuncAttributeMaxDynamicSharedMemorySize,
                         PROJ_SMEM_FLOATS * (int)sizeof(float));
    dim3 gp(DM / 128, MROWS / 128, 3);
    qkv_proj_tc<<<gp, 256, PROJ_SMEM_FLOATS * sizeof(float)>>>(X, Wq, bq, Wk, bk, Wv, bv);

    cudaFuncSetAttribute(attn_tc, cudaFuncAttributeMaxDynamicSharedMemorySize,
                         ATTN_SMEM_FLOATS * (int)sizeof(float));
    dim3 ga(SEQ / TQ, NH, NB);
    attn_tc<<<ga, NT, ATTN_SMEM_FLOATS * sizeof(float)>>>(mask, out);
}

// round 9
// speedup vs baseline: 2.8774x; 1.0170x over previous
#include <cuda_runtime.h>
#include <cstdint>

// Problem constants
#define NB   4
#define SEQ  1024
#define NH   16
#define DH   64
#define DM   1024
#define MROWS (NB * SEQ)

// Pre-split tf32 hi/lo copies of the GEMM inputs.
__device__ float g_xh[MROWS * DM], g_xl[MROWS * DM];
__device__ float g_wh[3 * DM * DM], g_wl[3 * DM * DM];

// Pre-split tf32 hi/lo Q/K ([B,H,S,DH], paired d-permutation) and V hi only
// ([B,H,DH,S] transposed, paired s-permutation).
__device__ float g_qh[NB * NH * SEQ * DH];
__device__ float g_ql[NB * NH * SEQ * DH];
__device__ float g_kh[NB * NH * SEQ * DH];
__device__ float g_kl[NB * NH * SEQ * DH];
__device__ float g_vh[NB * NH * SEQ * DH];

__device__ __forceinline__ int perm8(int x) { return ((x & 3) << 1) | ((x >> 2) & 1); }

__device__ __forceinline__ float to_tf32(float x) {
    unsigned u;
    asm("cvt.rna.tf32.f32 %0, %1;" : "=r"(u) : "f"(x));
    return __uint_as_float(u);
}
__device__ __forceinline__ void split_tf32(float x, float& hi, float& lo) {
    hi = to_tf32(x);
    lo = to_tf32(x - hi);
}
__device__ __forceinline__ void mma_tf32(float* c, const unsigned* a, const unsigned* b) {
    asm volatile(
        "mma.sync.aligned.m16n8k8.row.col.f32.tf32.tf32.f32 "
        "{%0,%1,%2,%3},{%4,%5,%6,%7},{%8,%9},{%0,%1,%2,%3};"
        : "+f"(c[0]), "+f"(c[1]), "+f"(c[2]), "+f"(c[3])
        : "r"(a[0]), "r"(a[1]), "r"(a[2]), "r"(a[3]), "r"(b[0]), "r"(b[1]));
}
__device__ __forceinline__ float warpMax(float v) {
#pragma unroll
    for (int o = 16; o > 0; o >>= 1) v = fmaxf(v, __shfl_xor_sync(0xffffffffu, v, o));
    return v;
}
__device__ __forceinline__ float warpSum(float v) {
#pragma unroll
    for (int o = 16; o > 0; o >>= 1) v += __shfl_xor_sync(0xffffffffu, v, o);
    return v;
}

#define CP_COMMIT() asm volatile("cp.async.commit_group;")
#define CP_WAIT(N)  asm volatile("cp.async.wait_group %0;" :: "n"(N))

__device__ __forceinline__ void cp16(float* dst, const float* src) {
    uint32_t a = (uint32_t)__cvta_generic_to_shared(dst);
    asm volatile("cp.async.cg.shared.global [%0], [%1], 16;" :: "r"(a), "l"(src));
}

// ---------------------------------------------------------------------------
// Pre-split X, Wq, Wk, Wv into tf32 hi/lo device arrays. Memory-bound.
// ---------------------------------------------------------------------------
__global__ __launch_bounds__(256) void presplit_kernel(
    const float* __restrict__ X, const float* __restrict__ Wq,
    const float* __restrict__ Wk, const float* __restrict__ Wv) {
    const size_t NX = (size_t)MROWS * DM / 4;
    const size_t NW = (size_t)DM * DM / 4;
    size_t i = (size_t)blockIdx.x * 256 + threadIdx.x;
    const float4* src;
    float4 *dh, *dl;
    size_t j;
    if (i < NX)               { src = (const float4*)X;  dh = (float4*)g_xh;      dl = (float4*)g_xl;      j = i; }
    else if (i < NX + NW)     { src = (const float4*)Wq; dh = (float4*)g_wh;      dl = (float4*)g_wl;      j = i - NX; }
    else if (i < NX + 2 * NW) { src = (const float4*)Wk; dh = (float4*)g_wh + NW; dl = (float4*)g_wl + NW; j = i - NX - NW; }
    else                      { src = (const float4*)Wv; dh = (float4*)g_wh + 2 * NW; dl = (float4*)g_wl + 2 * NW; j = i - NX - 2 * NW; }
    float4 v = src[j];
    float4 hv, lv;
    split_tf32(v.x, hv.x, lv.x); split_tf32(v.y, hv.y, lv.y);
    split_tf32(v.z, hv.z, lv.z); split_tf32(v.w, hv.w, lv.w);
    dh[j] = hv;
    dl[j] = lv;
}

// ---------------------------------------------------------------------------
// QKV projection, 3xTF32, cp.async double-buffered k-stages (no cvt in loop).
// CTA 128x128, k-stage 32, 8 warps, warp tile 64x32.
// ---------------------------------------------------------------------------
constexpr int PXS = 36;
constexpr int PWS = 136;
constexpr int XSTG = 128 * PXS;                 // 4608
constexpr int WSTG = 32 * PWS;                  // 4352
constexpr int STG  = 2 * XSTG + 2 * WSTG;       // 17920 floats per stage
constexpr int PROJ_SMEM_FLOATS = 2 * STG;       // 143.4 KB

__device__ __forceinline__ void proj_stage(float* s, const float* xh, const float* xl,
                                           const float* wh, const float* wl,
                                           int m0, int n0, int k0, int tid) {
    float* Xh = s;
    float* Xl = s + XSTG;
    float* Wh = s + 2 * XSTG;
    float* Wl = s + 2 * XSTG + WSTG;
#pragma unroll
    for (int it = 0; it < 4; ++it) {
        const int idx = tid + 256 * it;
        const int r = idx >> 3, c4 = (idx & 7) << 2;
        const size_t go = (size_t)(m0 + r) * DM + k0 + c4;
        cp16(Xh + r * PXS + c4, xh + go);
        cp16(Xl + r * PXS + c4, xl + go);
    }
#pragma unroll
    for (int it = 0; it < 4; ++it) {
        const int idx = tid + 256 * it;
        const int r = idx >> 5, c4 = (idx & 31) << 2;
        const size_t go = (size_t)(k0 + r) * DM + n0 + c4;
        cp16(Wh + r * PWS + c4, wh + go);
        cp16(Wl + r * PWS + c4, wl + go);
    }
}

__global__ __launch_bounds__(256) void qkv_proj_tc(
    const float* __restrict__ bq, const float* __restrict__ bk,
    const float* __restrict__ bv) {
    extern __shared__ float psm[];

    const int z = blockIdx.z;
    const float* wh = g_wh + (size_t)z * DM * DM;
    const float* wl = g_wl + (size_t)z * DM * DM;
    const float* bias = (z == 0) ? bq : (z == 1) ? bk : bv;
    float* outh = (z == 0) ? g_qh : (z == 1) ? g_kh : g_vh;
    float* outl = (z == 0) ? g_ql : g_kl;     // unused for V
    const bool isV = (z == 2);

    const int tid = threadIdx.x;
    const int warp = tid >> 5, lane = tid & 31;
    const int g = lane >> 2, t = lane & 3;
    const int wm = (warp >> 2) * 64, wn = (warp & 3) * 32;
    const int m0 = blockIdx.y * 128, n0 = blockIdx.x * 128;

    float acc[4][4][4] = {};

    proj_stage(psm, g_xh, g_xl, wh, wl, m0, n0, 0, tid);
    CP_COMMIT();

    for (int kb = 0; kb < DM / 32; ++kb) {
        CP_WAIT(0);
        __syncthreads();
        if (kb + 1 < DM / 32) {
            proj_stage(psm + ((kb + 1) & 1) * STG, g_xh, g_xl, wh, wl,
                       m0, n0, (kb + 1) * 32, tid);
            CP_COMMIT();
        }
        const float* Xh = psm + (kb & 1) * STG;
        const float* Xl = Xh + XSTG;
        const float* Wh = Xh + 2 * XSTG;
        const float* Wl = Xh + 2 * XSTG + WSTG;

#pragma unroll
        for (int ks = 0; ks < 4; ++ks) {
            unsigned ah[4][4], al[4][4], bh[4][2], bl[4][2];
#pragma unroll
            for (int i = 0; i < 4; ++i) {
                const int off = (wm + 16 * i + g) * PXS + 8 * ks + t;
                ah[i][0] = __float_as_uint(Xh[off]);
                ah[i][1] = __float_as_uint(Xh[off + 8 * PXS]);
                ah[i][2] = __float_as_uint(Xh[off + 4]);
                ah[i][3] = __float_as_uint(Xh[off + 8 * PXS + 4]);
                al[i][0] = __float_as_uint(Xl[off]);
                al[i][1] = __float_as_uint(Xl[off + 8 * PXS]);
                al[i][2] = __float_as_uint(Xl[off + 4]);
                al[i][3] = __float_as_uint(Xl[off + 8 * PXS + 4]);
            }
#pragma unroll
            for (int j = 0; j < 4; ++j) {
                const int off = (8 * ks + t) * PWS + wn + 8 * j + g;
                bh[j][0] = __float_as_uint(Wh[off]);
                bh[j][1] = __float_as_uint(Wh[off + 4 * PWS]);
                bl[j][0] = __float_as_uint(Wl[off]);
                bl[j][1] = __float_as_uint(Wl[off + 4 * PWS]);
            }
#pragma unroll
            for (int i = 0; i < 4; ++i)
#pragma unroll
                for (int j = 0; j < 4; ++j)
                    mma_tf32(acc[i][j], ah[i], bh[j]);
#pragma unroll
            for (int i = 0; i < 4; ++i)
#pragma unroll
                for (int j = 0; j < 4; ++j)
                    mma_tf32(acc[i][j], al[i], bh[j]);
#pragma unroll
            for (int i = 0; i < 4; ++i)
#pragma unroll
                for (int j = 0; j < 4; ++j)
                    mma_tf32(acc[i][j], ah[i], bl[j]);
        }
    }

    // epilogue: + bias, split, scatter into permuted layouts
#pragma unroll
    for (int j = 0; j < 4; ++j) {
        const int n = n0 + wn + 8 * j + 2 * t;
        const float b0v = bias[n], b1v = bias[n + 1];
        const int h = n >> 6, hd = n & 63;
        const int pd = (hd & ~7) | perm8(hd & 7);
#pragma unroll
        for (int i = 0; i < 4; ++i) {
            const int m = m0 + wm + 16 * i + g;
            const int bI = m >> 10, s = m & 1023;
            const int m2 = m + 8;
            const int bI2 = m2 >> 10, s2 = m2 & 1023;
            const float v0 = acc[i][j][0] + b0v;
            const float v1 = acc[i][j][1] + b1v;
            const float v2 = acc[i][j][2] + b0v;
            const float v3 = acc[i][j][3] + b1v;
            if (!isV) {
                float h0, l0, h1, l1, h2, l2, h3, l3;
                split_tf32(v0, h0, l0);
                split_tf32(v1, h1, l1);
                split_tf32(v2, h2, l2);
                split_tf32(v3, h3, l3);
                const size_t b1o = ((size_t)((bI * NH + h) * SEQ + s)) * DH;
                outh[b1o + pd] = h0;  outh[b1o + pd + 2] = h1;
                outl[b1o + pd] = l0;  outl[b1o + pd + 2] = l1;
                const size_t b2o = ((size_t)((bI2 * NH + h) * SEQ + s2)) * DH;
                outh[b2o + pd] = h2;  outh[b2o + pd + 2] = h3;
                outl[b2o + pd] = l2;  outl[b2o + pd + 2] = l3;
            } else {
                const int ps1 = (s & ~7) | perm8(s & 7);
                const int ps2 = (s2 & ~7) | perm8(s2 & 7);
                const size_t r0 = ((size_t)((bI * NH + h) * DH + hd)) * SEQ;
                const size_t r1 = ((size_t)((bI * NH + h) * DH + hd + 1)) * SEQ;
                outh[r0 + ps1] = to_tf32(v0);  outh[r1 + ps1] = to_tf32(v1);
                const size_t r0b = ((size_t)((bI2 * NH + h) * DH + hd)) * SEQ;
                const size_t r1b = ((size_t)((bI2 * NH + h) * DH + hd + 1)) * SEQ;
                outh[r0b + ps2] = to_tf32(v2);  outh[r1b + ps2] = to_tf32(v3);
            }
        }
    }
}

// ---------------------------------------------------------------------------
// Attention, 512 threads, cp.async double-buffer, 1 barrier/chunk.
// Phase 1: 3xTF32 QK^T. Phase 2: Michelot sparsemax / softmax.
// Phase 3: weights(tf32) @ V(tf32 hi only) — 8 MMAs/chunk, half staging.
// ---------------------------------------------------------------------------
constexpr int TQ  = 32;
constexpr int CK  = 64;
constexpr int NCH = SEQ / CK;     // 16
constexpr int NT  = 512;
constexpr int PS  = 72;
constexpr int SCP = 1032;
constexpr int KVSTG = CK * PS;
constexpr int ATTN_SMEM_FLOATS = TQ * SCP + 2 * TQ * PS + 4 * KVSTG;
constexpr float SCALE = 0.125f;

// hi+lo tile pair
__device__ __forceinline__ void stage_cp2(float* dh, float* dl,
                                          const float* gh, const float* gl,
                                          int tid, int gstride) {
#pragma unroll
    for (int it = 0; it < 2; ++it) {
        const int idx = tid + 512 * it;
        const int r = idx >> 4, c = (idx & 15) << 2;
        const int so = r * PS + c;
        const size_t go = (size_t)r * gstride + c;
        cp16(dh + so, gh + go);
        cp16(dl + so, gl + go);
    }
}
// hi only
__device__ __forceinline__ void stage_cp1(float* dh, const float* gh,
                                          int tid, int gstride) {
#pragma unroll
    for (int it = 0; it < 2; ++it) {
        const int idx = tid + 512 * it;
        const int r = idx >> 4, c = (idx & 15) << 2;
        cp16(dh + r * PS + c, gh + (size_t)r * gstride + c);
    }
}

__global__ __launch_bounds__(NT, 1) void attn_tc(const float* __restrict__ mask,
                                                 float* __restrict__ out) {
    extern __shared__ float sm[];
    float* sc  = sm;                    // [TQ][SCP]
    float* qsh = sm + TQ * SCP;         // [TQ][PS]
    float* qsl = qsh + TQ * PS;
    float* kv  = qsl + TQ * PS;

    float* kvH[2] = { kv, kv + 2 * KVSTG };
    float* kvL[2] = { kv + KVSTG, kv + 3 * KVSTG };

    const int tid = threadIdx.x;
    const int b = blockIdx.z, h = blockIdx.y;
    const int q0 = blockIdx.x * TQ;
    const int bh_i = b * NH + h;
    const float* Qh = g_qh + ((size_t)bh_i * SEQ + q0) * DH;
    const float* Ql = g_ql + ((size_t)bh_i * SEQ + q0) * DH;
    const float* Kh = g_kh + (size_t)bh_i * SEQ * DH;
    const float* Kl = g_kl + (size_t)bh_i * SEQ * DH;
    const float* Vh = g_vh + (size_t)bh_i * DH * SEQ;
    const float* mrow = mask + b * SEQ;

    const int warp = tid >> 5, lane = tid & 31;
    const int g = lane >> 2, t = lane & 3;
    const int wq = warp >> 3;
    const int wk = warp & 7;

    stage_cp2(kvH[0], kvL[0], Kh, Kl, tid, DH);
    CP_COMMIT();
    {
        const int e = tid << 2;
        const int qi = e >> 6, dd = e & 63;
        *(float4*)(qsh + qi * PS + dd) = *(const float4*)(Qh + e);
        *(float4*)(qsl + qi * PS + dd) = *(const float4*)(Ql + e);
    }
    __syncthreads();

    unsigned qah[8][4], qal[8][4];
#pragma unroll
    for (int ks = 0; ks < 8; ++ks) {
        const int off = (16 * wq + g) * PS + 8 * ks + 2 * t;
        float2 f0 = *(const float2*)(qsh + off);
        float2 f1 = *(const float2*)(qsh + off + 8 * PS);
        qah[ks][0] = __float_as_uint(f0.x);
        qah[ks][1] = __float_as_uint(f1.x);
        qah[ks][2] = __float_as_uint(f0.y);
        qah[ks][3] = __float_as_uint(f1.y);
        float2 e0 = *(const float2*)(qsl + off);
        float2 e1 = *(const float2*)(qsl + off + 8 * PS);
        qal[ks][0] = __float_as_uint(e0.x);
        qal[ks][1] = __float_as_uint(e1.x);
        qal[ks][2] = __float_as_uint(e0.y);
        qal[ks][3] = __float_as_uint(e1.y);
    }

    const int p0 = perm8(2 * t);

    // ---- phase 1: scores ----
    for (int kc = 0; kc < NCH; ++kc) {
        CP_WAIT(0);
        __syncthreads();
        if (kc + 1 < NCH) {
            stage_cp2(kvH[(kc + 1) & 1], kvL[(kc + 1) & 1],
                      Kh + (size_t)(kc + 1) * CK * DH, Kl + (size_t)(kc + 1) * CK * DH,
                      tid, DH);
            CP_COMMIT();
        }

        const float* bH = kvH[kc & 1];
        const float* bL = kvL[kc & 1];
        float a1[4] = {}, a2[4] = {}, a3[4] = {};
#pragma unroll
        for (int ks = 0; ks < 8; ++ks) {
            const int boff = (8 * wk + g) * PS + 8 * ks + 2 * t;
            float2 fb = *(const float2*)(bH + boff);
            float2 fl = *(const float2*)(bL + boff);
            unsigned bhf[2] = { __float_as_uint(fb.x), __float_as_uint(fb.y) };
            unsigned blf[2] = { __float_as_uint(fl.x), __float_as_uint(fl.y) };
            mma_tf32(a1, qah[ks], bhf);
            mma_tf32(a2, qal[ks], bhf);
            mma_tf32(a3, qah[ks], blf);
        }
        {
            const int bs = kc * CK + 8 * wk;
            const float2 mv = *(const float2*)(mrow + bs + 2 * t);
            const int q = 16 * wq + g;
            float c0 = a1[0] + a2[0] + a3[0];
            float c1 = a1[1] + a2[1] + a3[1];
            float c2 = a1[2] + a2[2] + a3[2];
            float c3 = a1[3] + a2[3] + a3[3];
            sc[q * SCP + bs + p0]           = fmaxf(fmaf(c0, SCALE, mv.x), -10000.0f);
            sc[q * SCP + bs + p0 + 2]       = fmaxf(fmaf(c1, SCALE, mv.y), -10000.0f);
            sc[(q + 8) * SCP + bs + p0]     = fmaxf(fmaf(c2, SCALE, mv.x), -10000.0f);
            sc[(q + 8) * SCP + bs + p0 + 2] = fmaxf(fmaf(c3, SCALE, mv.y), -10000.0f);
        }
    }

    stage_cp1(kvH[0], Vh, tid, SEQ);
    CP_COMMIT();
    __syncthreads();

    // ---- phase 2: Michelot sparsemax / softmax, 2 rows per warp ----
    {
        const bool sparse = ((h & 1) == 0);
        float* row0 = sc + warp * SCP;
        float* row1 = sc + (warp + 16) * SCP;
        float z0[32], z1[32];
#pragma unroll
        for (int j = 0; j < 32; ++j) { z0[j] = row0[j * 32 + lane]; z1[j] = row1[j * 32 + lane]; }
        float mx0 = -1e30f, mx1 = -1e30f;
#pragma unroll
        for (int j = 0; j < 32; ++j) { mx0 = fmaxf(mx0, z0[j]); mx1 = fmaxf(mx1, z1[j]); }
        mx0 = warpMax(mx0);
        mx1 = warpMax(mx1);

        if (sparse) {
            float tau0 = mx0 - 1.0f, tau1 = mx1 - 1.0f;
            for (int it = 0; it < 24; ++it) {
                float sa0 = 0.f, sb0 = 0.f, sc0 = 0.f, sd0 = 0.f;
                float ca0 = 0.f, cb0 = 0.f, cc0 = 0.f, cd0 = 0.f;
                float sa1 = 0.f, sb1 = 0.f, sc1 = 0.f, sd1 = 0.f;
                float ca1 = 0.f, cb1 = 0.f, cc1 = 0.f, cd1 = 0.f;
#pragma unroll
                for (int j = 0; j < 32; j += 4) {
                    if (z0[j]     > tau0) { sa0 += z0[j];     ca0 += 1.f; }
                    if (z0[j + 1] > tau0) { sb0 += z0[j + 1]; cb0 += 1.f; }
                    if (z0[j + 2] > tau0) { sc0 += z0[j + 2]; cc0 += 1.f; }
                    if (z0[j + 3] > tau0) { sd0 += z0[j + 3]; cd0 += 1.f; }
                    if (z1[j]     > tau1) { sa1 += z1[j];     ca1 += 1.f; }
                    if (z1[j + 1] > tau1) { sb1 += z1[j + 1]; cb1 += 1.f; }
                    if (z1[j + 2] > tau1) { sc1 += z1[j + 2]; cc1 += 1.f; }
                    if (z1[j + 3] > tau1) { sd1 += z1[j + 3]; cd1 += 1.f; }
                }
                float s0 = (sa0 + sb0) + (sc0 + sd0);
                float c0 = (ca0 + cb0) + (cc0 + cd0);
                float s1 = (sa1 + sb1) + (sc1 + sd1);
                float c1 = (ca1 + cb1) + (cc1 + cd1);
                s0 = warpSum(s0);
                c0 = warpSum(c0);
                s1 = warpSum(s1);
                c1 = warpSum(c1);
                const float nt0 = (s0 - 1.0f) / c0;
                const float nt1 = (s1 - 1.0f) / c1;
                const bool done = (nt0 == tau0) && (nt1 == tau1);
                tau0 = nt0;
                tau1 = nt1;
                if (done) break;
            }
#pragma unroll
            for (int j = 0; j < 32; ++j) {
                row0[j * 32 + lane] = to_tf32(fmaxf(z0[j] - tau0, 0.f));
                row1[j * 32 + lane] = to_tf32(fmaxf(z1[j] - tau1, 0.f));
            }
        } else {
            float s0 = 0.f, s1 = 0.f;
#pragma unroll
            for (int j = 0; j < 32; ++j) {
                z0[j] = __expf(z0[j] - mx0); s0 += z0[j];
                z1[j] = __expf(z1[j] - mx1); s1 += z1[j];
            }
            s0 = warpSum(s0);
            s1 = warpSum(s1);
            const float i0 = 1.0f / s0, i1 = 1.0f / s1;
#pragma unroll
            for (int j = 0; j < 32; ++j) {
                row0[j * 32 + lane] = to_tf32(z0[j] * i0);
                row1[j * 32 + lane] = to_tf32(z1[j] * i1);
            }
        }
    }

    // ---- phase 3: out = weights @ V (hi only), 2 accumulator chains ----
    float o1[4] = {}, o2[4] = {};
    for (int kc = 0; kc < NCH; ++kc) {
        CP_WAIT(0);
        __syncthreads();
        if (kc + 1 < NCH) {
            stage_cp1(kvH[(kc + 1) & 1], Vh + (kc + 1) * CK, tid, SEQ);
            CP_COMMIT();
        }

        const float* bH = kvH[kc & 1];
#pragma unroll
        for (int kk = 0; kk < CK / 8; ++kk) {
            const float* ap = sc + (16 * wq + g) * SCP + kc * CK + 8 * kk + 2 * t;
            float2 fa0 = *(const float2*)(ap);
            float2 fa1 = *(const float2*)(ap + 8 * SCP);
            unsigned a[4] = { __float_as_uint(fa0.x), __float_as_uint(fa1.x),
                              __float_as_uint(fa0.y), __float_as_uint(fa1.y) };
            const int boff = (8 * wk + g) * PS + 8 * kk + 2 * t;
            float2 fbh = *(const float2*)(bH + boff);
            unsigned bhf[2] = { __float_as_uint(fbh.x), __float_as_uint(fbh.y) };
            mma_tf32((kk & 1) ? o2 : o1, a, bhf);
        }
    }

    // write [B, S, H*HD]
    {
        const int q = q0 + 16 * wq + g;
        float* p = out + (size_t)(b * SEQ + q) * DM + h * DH + 8 * wk + 2 * t;
        *(float2*)p = make_float2(o1[0] + o2[0], o1[1] + o2[1]);
        *(float2*)(p + 8 * DM) = make_float2(o1[2] + o2[2], o1[3] + o2[3]);
    }
}

// ---------------------------------------------------------------------------
extern "C" void kernel_launch(void* const* d_in, const int* in_sizes, int n_in,
                              void* d_out, int out_size) {
    const float* X    = (const float*)d_in[0];
    const float* Wq   = (const float*)d_in[1];
    const float* bq   = (const float*)d_in[2];
    const float* Wk   = (const float*)d_in[3];
    const float* bk   = (const float*)d_in[4];
    const float* Wv   = (const float*)d_in[5];
    const float* bv   = (const float*)d_in[6];
    const float* mask = (const float*)d_in[7];
    float* out = (float*)d_out;

    const int nsplit = (MROWS * DM + 3 * DM * DM) / 4;
    presplit_kernel<<<nsplit / 256, 256>>>(X, Wq, Wk, Wv);

    cudaFuncSetAttribute(qkv_proj_tc, cudaFuncAttributeMaxDynamicSharedMemorySize,
                         PROJ_SMEM_FLOATS * (int)sizeof(float));
    dim3 gp(DM / 128, MROWS / 128, 3);
    qkv_proj_tc<<<gp, 256, PROJ_SMEM_FLOATS * sizeof(float)>>>(bq, bk, bv);

    cudaFuncSetAttribute(attn_tc, cudaFuncAttributeMaxDynamicSharedMemorySize,
                         ATTN_SMEM_FLOATS * (int)sizeof(float));
    dim3 ga(SEQ / TQ, NH, NB);
    attn_tc<<<ga, NT, ATTN_SMEM_FLOATS * sizeof(float)>>>(mask, out);
}